// round 13
// baseline (speedup 1.0000x reference)
#include <cuda_runtime.h>
#include <cuda_bf16.h>
#include <math.h>
#include <stdint.h>

#define NL 6
#define NB 4
#define SEQ 2048
#define DM 1024
#define DI 2048
#define DS 16
#define DR 64
#define NTOK (NB*SEQ)   // 8192
#define NCH 16          // scan chunks per sequence
#define CL (SEQ/NCH)    // 128 steps per chunk

// ---------------- scratch (device globals; no allocations allowed) ----------
__device__ float g_x[NTOK*DM];
__device__ float g_xz[NTOK*2*DI];
__device__ float g_xi[NTOK*DI];
__device__ float g_xdbl[NTOK*96];
__device__ float g_delta[NTOK*DI];
__device__ float g_tmp[NTOK*DM];
__device__ float g_tmp4[NB*DM];
__device__ float g_ypart[NTOK*DI];
__device__ float g_ap[NB*DI*NCH*DS];
__device__ float g_he[NB*DI*NCH*DS];
__device__ float g_h0[NB*DI*NCH*DS];

__device__ __nv_bfloat16 g_xbf[NTOK*DM];
__device__ __nv_bfloat16 g_xibf[NTOK*DI];
__device__ __nv_bfloat16 g_ybf[NTOK*DI];
__device__ __nv_bfloat16 g_xdblbf[NTOK*96];
__device__ __nv_bfloat16 g_inw_bf[NL*2*DI*DM];
__device__ __nv_bfloat16 g_xpw_bf[NL*96*DI];
__device__ __nv_bfloat16 g_dtw_bf[NL*DI*DR];
__device__ __nv_bfloat16 g_outw_bf[NL*DM*DI];

// -------------------------- math helpers ------------------------------------
__device__ __forceinline__ float siluf(float x) { return x / (1.0f + __expf(-x)); }
// fast e^x (accurate for x <= 0), FMA-pipe only
__device__ __forceinline__ float fexp(float x) {
    float y = x * 1.4426950408889634f;
    float t = y + 12582912.0f;
    int   e = (__float_as_int(t) & 0x7FFFFF) - 0x400000;
    float f = y - (t - 12582912.0f);
    float p = 1.5403530e-4f;
    p = fmaf(p, f, 1.3333558e-3f);
    p = fmaf(p, f, 9.6181291e-3f);
    p = fmaf(p, f, 5.5504109e-2f);
    p = fmaf(p, f, 2.4022651e-1f);
    p = fmaf(p, f, 6.9314718e-1f);
    p = fmaf(p, f, 1.0f);
    if (e < -120) return 0.0f;
    return __int_as_float(__float_as_int(p) + (e << 23));
}
__device__ __forceinline__ float softp(float x) {
    return fmaxf(x, 0.0f) + log1pf(fexp(-fabsf(x)));
}
__device__ __forceinline__ uint32_t smem_u32(const void* p) {
    uint32_t a;
    asm("{ .reg .u64 t; cvta.to.shared.u64 t, %1; cvt.u32.u64 %0, t; }" : "=r"(a) : "l"(p));
    return a;
}
__device__ __forceinline__ void cp16(uint32_t dst, const void* src) {
    asm volatile("cp.async.cg.shared.global [%0], [%1], 16;" :: "r"(dst), "l"(src) : "memory");
}
__device__ __forceinline__ void mma_bf16(float* d, const uint32_t* a, const uint32_t* b) {
    asm volatile(
        "mma.sync.aligned.m16n8k16.row.col.f32.bf16.bf16.f32 "
        "{%0,%1,%2,%3}, {%4,%5,%6,%7}, {%8,%9}, {%0,%1,%2,%3};"
        : "+f"(d[0]), "+f"(d[1]), "+f"(d[2]), "+f"(d[3])
        : "r"(a[0]), "r"(a[1]), "r"(a[2]), "r"(a[3]), "r"(b[0]), "r"(b[1]));
}
__device__ __forceinline__ void ldsm4(uint32_t addr, uint32_t& r0, uint32_t& r1,
                                      uint32_t& r2, uint32_t& r3) {
    asm volatile("ldmatrix.sync.aligned.m8n8.x4.shared.b16 {%0,%1,%2,%3}, [%4];"
                 : "=r"(r0), "=r"(r1), "=r"(r2), "=r"(r3) : "r"(addr));
}

// ---------------------------------------------------------------------------
// bf16 mma.sync GEMM:  C[M,N] = A[M,K] * B[N,K]^T   (both bf16, K-contiguous)
// 128x128 CTA tile, BK=32, 128 threads (4 warps, 2x2 grid, 64x64 warp tiles),
// cp.async double-buffered staging, ldmatrix.x4 frag loads (1 LDSM : 4 MMA),
// __launch_bounds__(128,2) => 2 CTAs/SM.
// Rows padded to 40 halves (80B) => conflict-free LDSM phases.
// MODE 0: fp32 store.  MODE 1: softplus(acc+bias).  MODE 2: fp32 + bf16 copy.
// ---------------------------------------------------------------------------
template<int MODE>
__global__ __launch_bounds__(128, 2) void bgemm(
    const __nv_bfloat16* __restrict__ A, const __nv_bfloat16* __restrict__ Bw,
    float* __restrict__ C, __nv_bfloat16* __restrict__ Cb,
    const float* __restrict__ bias,
    int M, int N, int K, int lda, int ldb, int ldc)
{
    constexpr int BK = 32, LDS_ = BK + 8;   // 40 halves = 80B row stride
    constexpr int MT = 4, NT = 8;           // warp tile 64x64

    __shared__ __nv_bfloat16 As[2][128][LDS_];
    __shared__ __nv_bfloat16 Bs[2][128][LDS_];

    const int tid = threadIdx.x, lane = tid & 31, warp = tid >> 5;
    const int m0 = blockIdx.y * 128, n0 = blockIdx.x * 128;
    const int wm = (warp >> 1) * 64, wn = (warp & 1) * 64;
    const int grp = lane >> 2, thr = lane & 3;

    // ldmatrix source coordinates (within tile, before buf offset)
    const int a_row = wm + (lane & 15);                      // + mt*16
    const int a_col = (lane >> 4) * 8;                       // + kk
    const int b_row = wn + (lane & 7) + ((lane >> 4) << 3);  // + np*16
    const int b_col = ((lane >> 3) & 1) * 8;                 // + kk

    const uint32_t sA = smem_u32(&As[0][0][0]);
    const uint32_t sB = smem_u32(&Bs[0][0][0]);
    constexpr uint32_t BUF = 128 * LDS_ * 2;

    float acc[MT][NT][4];
#pragma unroll
    for (int i = 0; i < MT; i++)
#pragma unroll
        for (int j = 0; j < NT; j++)
#pragma unroll
            for (int q = 0; q < 4; q++) acc[i][j][q] = 0.0f;

    auto stage = [&](int kt, int buf) {
        int k0 = kt << 5;
#pragma unroll
        for (int i = 0; i < 4; i++) {
            int idx = tid + (i << 7);
            int r = idx >> 2, c = idx & 3;
            cp16(smem_u32(&As[buf][r][c * 8]),
                 A + (size_t)(m0 + r) * lda + k0 + c * 8);
        }
#pragma unroll
        for (int i = 0; i < 4; i++) {
            int idx = tid + (i << 7);
            int r = idx >> 2, c = idx & 3;
            int gr = n0 + r; if (gr >= N) gr = N - 1;
            cp16(smem_u32(&Bs[buf][r][c * 8]),
                 Bw + (size_t)gr * ldb + k0 + c * 8);
        }
        asm volatile("cp.async.commit_group;" ::: "memory");
    };

    auto comp = [&](int buf) {
        uint32_t aB = sA + buf * BUF;
        uint32_t bB = sB + buf * BUF;
#pragma unroll
        for (int kk = 0; kk < BK; kk += 16) {
            uint32_t af[MT][4], bf[NT][2];
#pragma unroll
            for (int mt = 0; mt < MT; mt++)
                ldsm4(aB + (uint32_t)(((a_row + mt * 16) * LDS_ + kk + a_col) * 2),
                      af[mt][0], af[mt][1], af[mt][2], af[mt][3]);
#pragma unroll
            for (int np = 0; np < NT / 2; np++)
                ldsm4(bB + (uint32_t)(((b_row + np * 16) * LDS_ + kk + b_col) * 2),
                      bf[2 * np][0], bf[2 * np][1], bf[2 * np + 1][0], bf[2 * np + 1][1]);
#pragma unroll
            for (int mt = 0; mt < MT; mt++)
#pragma unroll
                for (int nt = 0; nt < NT; nt++)
                    mma_bf16(acc[mt][nt], af[mt], bf[nt]);
        }
    };

    const int NC = K >> 5;
    stage(0, 0);
    for (int kt = 0; kt < NC; kt++) {
        int buf = kt & 1;
        if (kt + 1 < NC) {
            stage(kt + 1, buf ^ 1);
            asm volatile("cp.async.wait_group 1;" ::: "memory");
        } else {
            asm volatile("cp.async.wait_group 0;" ::: "memory");
        }
        __syncthreads();
        comp(buf);
        __syncthreads();
    }

#pragma unroll
    for (int mt = 0; mt < MT; mt++) {
        int r0 = m0 + wm + mt * 16 + grp;
#pragma unroll
        for (int nt = 0; nt < NT; nt++) {
            int c0 = n0 + wn + nt * 8 + thr * 2;
            if (c0 < N) {
                float v0 = acc[mt][nt][0], v1 = acc[mt][nt][1];
                float v2 = acc[mt][nt][2], v3 = acc[mt][nt][3];
                if (MODE == 1) {
                    float b0 = bias[c0], b1 = bias[c0 + 1];
                    v0 = softp(v0 + b0); v1 = softp(v1 + b1);
                    v2 = softp(v2 + b0); v3 = softp(v3 + b1);
                }
                *(float2*)&C[(size_t)r0 * ldc + c0]       = make_float2(v0, v1);
                *(float2*)&C[(size_t)(r0 + 8) * ldc + c0] = make_float2(v2, v3);
                if (MODE == 2) {
                    __nv_bfloat162 h0, h1;
                    h0.x = __float2bfloat16(v0); h0.y = __float2bfloat16(v1);
                    h1.x = __float2bfloat16(v2); h1.y = __float2bfloat16(v3);
                    *(__nv_bfloat162*)&Cb[(size_t)r0 * ldc + c0]       = h0;
                    *(__nv_bfloat162*)&Cb[(size_t)(r0 + 8) * ldc + c0] = h1;
                }
            }
        }
    }
}

// ---------------------------------------------------------------------------
__global__ void f2bf_all(const float* __restrict__ s1, const float* __restrict__ s2,
                         const float* __restrict__ s3, const float* __restrict__ s4,
                         __nv_bfloat16* __restrict__ d1, __nv_bfloat16* __restrict__ d2,
                         __nv_bfloat16* __restrict__ d3, __nv_bfloat16* __restrict__ d4,
                         int n1, int n2, int n3, int n4)
{
    int i = blockIdx.x * blockDim.x + threadIdx.x;
    if (i < n1) { d1[i] = __float2bfloat16(s1[i]); return; }
    i -= n1;
    if (i < n2) { d2[i] = __float2bfloat16(s2[i]); return; }
    i -= n2;
    if (i < n3) { d3[i] = __float2bfloat16(s3[i]); return; }
    i -= n3;
    if (i < n4) d4[i] = __float2bfloat16(s4[i]);
}
__global__ void copy_kernel(const float* __restrict__ src, float* __restrict__ dst,
                            __nv_bfloat16* __restrict__ dstb, int n)
{
    int i = blockIdx.x * blockDim.x + threadIdx.x;
    if (i < n) { float v = src[i]; dst[i] = v; dstb[i] = __float2bfloat16(v); }
}

// Causal depthwise conv (width 4) + bias + SiLU; fp32 + bf16 outputs.
__global__ void conv_silu_kernel(const float* __restrict__ xz,
                                 const float* __restrict__ cw,
                                 const float* __restrict__ cb,
                                 float* __restrict__ xi,
                                 __nv_bfloat16* __restrict__ xib)
{
    int idx = blockIdx.x * blockDim.x + threadIdx.x;
    if (idx >= NTOK * DI) return;
    int d = idx % DI;
    int n = idx / DI;
    int t = n % SEQ;
    float acc = cb[d];
#pragma unroll
    for (int k = 0; k < 4; k++) {
        int tt = t - 3 + k;
        if (tt >= 0)
            acc = fmaf(cw[d * 4 + k], xz[(size_t)(n - 3 + k) * (2 * DI) + d], acc);
    }
    float v = siluf(acc);
    xi[idx] = v;
    xib[idx] = __float2bfloat16(v);
}

// ---------------------------------------------------------------------------
// Chunked selective scan (validated R11 structure).
// ---------------------------------------------------------------------------
__device__ __forceinline__ void scan_coeffs(
    const float* A_log, int d, int sub, float* Av, bool& trick)
{
#pragma unroll
    for (int i = 0; i < 4; i++)
        Av[i] = -__expf(A_log[d * DS + sub * 4 + i]);
    int e0 = sub * 4 + 1;
    trick = true;
#pragma unroll
    for (int i = 0; i < 4; i++)
        trick = trick && (fabsf(Av[i] + (float)(e0 + i)) < 3e-4f * (float)(e0 + i));
}
__device__ __forceinline__ void scan_dA(bool trick, const float* Av, int sub,
                                        float dlt, float* a)
{
    if (trick) {
        float r = fexp(-dlt);
        float r2 = r * r, r4 = r2 * r2;
        float p = r;
        if (sub & 1) p *= r4;
        if (sub & 2) p *= r4 * r4;
        a[0] = p; a[1] = p * r; a[2] = a[1] * r; a[3] = a[2] * r;
    } else {
        a[0] = fexp(dlt * Av[0]); a[1] = fexp(dlt * Av[1]);
        a[2] = fexp(dlt * Av[2]); a[3] = fexp(dlt * Av[3]);
    }
}

__global__ __launch_bounds__(128) void scanA(
    const float* __restrict__ xdbl, const float* __restrict__ delta,
    const float* __restrict__ xi, const float* __restrict__ A_log,
    float* __restrict__ ypart, float* __restrict__ apv, float* __restrict__ hev)
{
    int gt  = blockIdx.x * 128 + threadIdx.x;
    int sub = gt & 3;
    int ch  = gt >> 2;                 // (b*DI+d)*NCH + c
    if (ch >= NB * DI * NCH) return;
    int c  = ch % NCH;
    int bd = ch / NCH;
    int d  = bd % DI, b = bd / DI;

    float Av[4]; bool trick;
    scan_coeffs(A_log, d, sub, Av, trick);

    float h[4] = {0.f, 0.f, 0.f, 0.f};
    float ap[4] = {1.f, 1.f, 1.f, 1.f};
    const int base = b * SEQ + c * CL;

    for (int t = 0; t < CL; t++) {
        int n = base + t;
        float dlt = __ldg(&delta[(size_t)n * DI + d]);
        float u   = __ldg(&xi[(size_t)n * DI + d]);
        float4 Bv = __ldg((const float4*)(xdbl + (size_t)n * 96 + 64 + sub * 4));
        float4 Cv = __ldg((const float4*)(xdbl + (size_t)n * 96 + 80 + sub * 4));
        float a[4];
        scan_dA(trick, Av, sub, dlt, a);
        float du = dlt * u;
#pragma unroll
        for (int i = 0; i < 4; i++) ap[i] *= a[i];
        h[0] = fmaf(a[0], h[0], Bv.x * du);
        h[1] = fmaf(a[1], h[1], Bv.y * du);
        h[2] = fmaf(a[2], h[2], Bv.z * du);
        h[3] = fmaf(a[3], h[3], Bv.w * du);
        float yp = h[0] * Cv.x;
        yp = fmaf(h[1], Cv.y, yp);
        yp = fmaf(h[2], Cv.z, yp);
        yp = fmaf(h[3], Cv.w, yp);
        yp += __shfl_xor_sync(0xffffffffu, yp, 1);
        yp += __shfl_xor_sync(0xffffffffu, yp, 2);
        if (sub == 0) ypart[(size_t)n * DI + d] = yp;
    }
#pragma unroll
    for (int i = 0; i < 4; i++) {
        apv[ch * 16 + sub * 4 + i] = ap[i];
        hev[ch * 16 + sub * 4 + i] = h[i];
    }
}

__global__ void scanB(const float* __restrict__ apv, const float* __restrict__ hev,
                      float* __restrict__ h0v)
{
    int i = blockIdx.x * 256 + threadIdx.x;   // over NB*DI*DS
    if (i >= NB * DI * DS) return;
    int s  = i & 15;
    int bd = i >> 4;
    float h = 0.0f;
#pragma unroll
    for (int c = 0; c < NCH; c++) {
        int idx = (bd * NCH + c) * 16 + s;
        h0v[idx] = h;
        h = fmaf(apv[idx], h, hev[idx]);
    }
}

__global__ __launch_bounds__(128) void scanC(
    const float* __restrict__ xdbl, const float* __restrict__ delta,
    const float* __restrict__ xi, const float* __restrict__ xz,
    const float* __restrict__ A_log, const float* __restrict__ Dv,
    const float* __restrict__ ypart, const float* __restrict__ h0v,
    __nv_bfloat16* __restrict__ ybf)
{
    int gt  = blockIdx.x * 128 + threadIdx.x;
    int sub = gt & 3;
    int ch  = gt >> 2;
    if (ch >= NB * DI * NCH) return;
    int c  = ch % NCH;
    int bd = ch / NCH;
    int d  = bd % DI, b = bd / DI;

    float Av[4]; bool trick;
    scan_coeffs(A_log, d, sub, Av, trick);
    float Dd = Dv[d];

    float h0[4], P[4] = {1.f, 1.f, 1.f, 1.f};
#pragma unroll
    for (int i = 0; i < 4; i++) h0[i] = h0v[ch * 16 + sub * 4 + i];

    const int base = b * SEQ + c * CL;
    for (int t = 0; t < CL; t++) {
        int n = base + t;
        float dlt = __ldg(&delta[(size_t)n * DI + d]);
        float4 Cv = __ldg((const float4*)(xdbl + (size_t)n * 96 + 80 + sub * 4));
        float a[4];
        scan_dA(trick, Av, sub, dlt, a);
#pragma unroll
        for (int i = 0; i < 4; i++) P[i] *= a[i];
        float corr = (P[0] * h0[0]) * Cv.x;
        corr = fmaf(P[1] * h0[1], Cv.y, corr);
        corr = fmaf(P[2] * h0[2], Cv.z, corr);
        corr = fmaf(P[3] * h0[3], Cv.w, corr);
        corr += __shfl_xor_sync(0xffffffffu, corr, 1);
        corr += __shfl_xor_sync(0xffffffffu, corr, 2);
        if (sub == 0) {
            float y = ypart[(size_t)n * DI + d] + corr;
            float u = __ldg(&xi[(size_t)n * DI + d]);
            float zv = __ldg(&xz[(size_t)n * (2 * DI) + DI + d]);
            ybf[(size_t)n * DI + d] = __float2bfloat16((y + u * Dd) * siluf(zv));
        }
    }
}

// LayerNorm with fused residual: x = LN(tmp + x)*w + b; fp32 + bf16 outputs.
__global__ __launch_bounds__(256) void ln_kernel(
    const float* __restrict__ tmp, float* __restrict__ x,
    __nv_bfloat16* __restrict__ xb,
    const float* __restrict__ w, const float* __restrict__ bb)
{
    int n = blockIdx.x;
    int tid = threadIdx.x;
    __shared__ float sred[40];

    float v[4];
    float s = 0.0f;
#pragma unroll
    for (int i = 0; i < 4; i++) {
        int c = tid + 256 * i;
        v[i] = tmp[(size_t)n * DM + c] + x[(size_t)n * DM + c];
        s += v[i];
    }
    for (int o = 16; o; o >>= 1) s += __shfl_xor_sync(0xffffffffu, s, o);
    if ((tid & 31) == 0) sred[tid >> 5] = s;
    __syncthreads();
    if (tid < 8) {
        s = sred[tid];
        for (int o = 4; o; o >>= 1) s += __shfl_xor_sync(0xffu, s, o);
        if (tid == 0) sred[32] = s;
    }
    __syncthreads();
    float mu = sred[32] * (1.0f / DM);

    float s2 = 0.0f;
#pragma unroll
    for (int i = 0; i < 4; i++) {
        float dv = v[i] - mu;
        s2 += dv * dv;
    }
    for (int o = 16; o; o >>= 1) s2 += __shfl_xor_sync(0xffffffffu, s2, o);
    if ((tid & 31) == 0) sred[tid >> 5] = s2;
    __syncthreads();
    if (tid < 8) {
        s2 = sred[tid];
        for (int o = 4; o; o >>= 1) s2 += __shfl_xor_sync(0xffu, s2, o);
        if (tid == 0) sred[33] = s2;
    }
    __syncthreads();
    float inv = rsqrtf(sred[33] * (1.0f / DM) + 1e-5f);

#pragma unroll
    for (int i = 0; i < 4; i++) {
        int c = tid + 256 * i;
        float o = (v[i] - mu) * inv * w[c] + bb[c];
        x[(size_t)n * DM + c] = o;
        xb[(size_t)n * DM + c] = __float2bfloat16(o);
    }
}

// Layer-6 shortcut: out_proj restricted to last token of each batch.
__global__ __launch_bounds__(256) void final_out_kernel(
    const __nv_bfloat16* __restrict__ y, const __nv_bfloat16* __restrict__ outw,
    float* __restrict__ tmp4)
{
    int b = blockIdx.x, col = blockIdx.y * 256 + threadIdx.x;
    const __nv_bfloat16* yr = y + (size_t)(b * SEQ + SEQ - 1) * DI;
    const __nv_bfloat16* wr = outw + (size_t)col * DI;
    __shared__ __nv_bfloat16 ys[DI];
    for (int i = threadIdx.x; i < DI; i += 256) ys[i] = yr[i];
    __syncthreads();
    float s = 0.0f;
#pragma unroll 4
    for (int k = 0; k < DI; k += 8) {
        uint4 wv = *(const uint4*)(wr + k);
        const __nv_bfloat162* w2 = (const __nv_bfloat162*)&wv;
        const __nv_bfloat162* y2 = (const __nv_bfloat162*)&ys[k];
#pragma unroll
        for (int j = 0; j < 4; j++) {
            s = fmaf(__bfloat162float(y2[j].x), __bfloat162float(w2[j].x), s);
            s = fmaf(__bfloat162float(y2[j].y), __bfloat162float(w2[j].y), s);
        }
    }
    tmp4[b * DM + col] = s;
}

// Layer-6 LN + prediction fused, last tokens only.
__global__ __launch_bounds__(256) void final_ln_pred(
    const float* __restrict__ tmp4, const float* __restrict__ x,
    const float* __restrict__ w, const float* __restrict__ bb,
    const float* __restrict__ pw, const float* __restrict__ pb,
    float* __restrict__ out)
{
    int b = blockIdx.x;
    int tid = threadIdx.x;
    __shared__ float sred[40];
    const float* row = x + (size_t)(b * SEQ + SEQ - 1) * DM;

    float v[4];
    float s = 0.0f;
#pragma unroll
    for (int i = 0; i < 4; i++) {
        int c = tid + 256 * i;
        v[i] = tmp4[b * DM + c] + row[c];
        s += v[i];
    }
    for (int o = 16; o; o >>= 1) s += __shfl_xor_sync(0xffffffffu, s, o);
    if ((tid & 31) == 0) sred[tid >> 5] = s;
    __syncthreads();
    if (tid < 8) {
        s = sred[tid];
        for (int o = 4; o; o >>= 1) s += __shfl_xor_sync(0xffu, s, o);
        if (tid == 0) sred[32] = s;
    }
    __syncthreads();
    float mu = sred[32] * (1.0f / DM);

    float s2 = 0.0f;
#pragma unroll
    for (int i = 0; i < 4; i++) { float dv = v[i] - mu; s2 += dv * dv; }
    for (int o = 16; o; o >>= 1) s2 += __shfl_xor_sync(0xffffffffu, s2, o);
    if ((tid & 31) == 0) sred[tid >> 5] = s2;
    __syncthreads();
    if (tid < 8) {
        s2 = sred[tid];
        for (int o = 4; o; o >>= 1) s2 += __shfl_xor_sync(0xffu, s2, o);
        if (tid == 0) sred[33] = s2;
    }
    __syncthreads();
    float inv = rsqrtf(sred[33] * (1.0f / DM) + 1e-5f);

    float s3 = 0.0f;
#pragma unroll
    for (int i = 0; i < 4; i++) {
        int c = tid + 256 * i;
        float o = (v[i] - mu) * inv * w[c] + bb[c];
        s3 = fmaf(o, pw[c], s3);
    }
    for (int o = 16; o; o >>= 1) s3 += __shfl_xor_sync(0xffffffffu, s3, o);
    if ((tid & 31) == 0) sred[tid >> 5] = s3;
    __syncthreads();
    if (tid < 8) {
        s3 = sred[tid];
        for (int o = 4; o; o >>= 1) s3 += __shfl_xor_sync(0xffu, s3, o);
        if (tid == 0) out[b] = s3 + pb[0];
    }
}

// ---------------------------------------------------------------------------
extern "C" void kernel_launch(void* const* d_in, const int* in_sizes, int n_in,
                              void* d_out, int out_size)
{
    const float* x_in  = (const float*)d_in[0];
    const float* inw   = (const float*)d_in[1];
    const float* convw = (const float*)d_in[2];
    const float* convb = (const float*)d_in[3];
    const float* xpw   = (const float*)d_in[4];
    const float* dtw   = (const float*)d_in[5];
    const float* dtb   = (const float*)d_in[6];
    const float* Alog  = (const float*)d_in[7];
    const float* Dv    = (const float*)d_in[8];
    const float* outw  = (const float*)d_in[9];
    const float* lnw   = (const float*)d_in[10];
    const float* lnb   = (const float*)d_in[11];
    const float* predw = (const float*)d_in[12];
    const float* predb = (const float*)d_in[13];
    float* out = (float*)d_out;

    float *p_x, *p_xz, *p_xi, *p_xdbl, *p_delta, *p_tmp, *p_tmp4;
    float *p_ypart, *p_ap, *p_he, *p_h0;
    __nv_bfloat16 *p_xbf, *p_xibf, *p_ybf, *p_xdblbf;
    __nv_bfloat16 *p_inwb, *p_xpwb, *p_dtwb, *p_outwb;
    cudaGetSymbolAddress((void**)&p_x, g_x);
    cudaGetSymbolAddress((void**)&p_xz, g_xz);
    cudaGetSymbolAddress((void**)&p_xi, g_xi);
    cudaGetSymbolAddress((void**)&p_xdbl, g_xdbl);
    cudaGetSymbolAddress((void**)&p_delta, g_delta);
    cudaGetSymbolAddress((void**)&p_tmp, g_tmp);
    cudaGetSymbolAddress((void**)&p_tmp4, g_tmp4);
    cudaGetSymbolAddress((void**)&p_ypart, g_ypart);
    cudaGetSymbolAddress((void**)&p_ap, g_ap);
    cudaGetSymbolAddress((void**)&p_he, g_he);
    cudaGetSymbolAddress((void**)&p_h0, g_h0);
    cudaGetSymbolAddress((void**)&p_xbf, g_xbf);
    cudaGetSymbolAddress((void**)&p_xibf, g_xibf);
    cudaGetSymbolAddress((void**)&p_ybf, g_ybf);
    cudaGetSymbolAddress((void**)&p_xdblbf, g_xdblbf);
    cudaGetSymbolAddress((void**)&p_inwb, g_inw_bf);
    cudaGetSymbolAddress((void**)&p_xpwb, g_xpw_bf);
    cudaGetSymbolAddress((void**)&p_dtwb, g_dtw_bf);
    cudaGetSymbolAddress((void**)&p_outwb, g_outw_bf);

    // One launch for all weight conversions
    {
        int n1 = NL * 2 * DI * DM, n2 = NL * 96 * DI, n3 = NL * DI * DR, n4 = NL * DM * DI;
        int nt = n1 + n2 + n3 + n4;
        f2bf_all<<<(nt + 255) / 256, 256>>>(inw, xpw, dtw, outw,
                                            p_inwb, p_xpwb, p_dtwb, p_outwb,
                                            n1, n2, n3, n4);
    }
    copy_kernel<<<(NTOK * DM + 255) / 256, 256>>>(x_in, p_x, p_xbf, NTOK * DM);

    for (int l = 0; l < NL; l++) {
        // 1) xz = x @ in_proj_w^T
        bgemm<0><<<dim3((2 * DI) / 128, NTOK / 128), 128>>>(
            p_xbf, p_inwb + (size_t)l * 2 * DI * DM, p_xz, nullptr, nullptr,
            NTOK, 2 * DI, DM, DM, DM, 2 * DI);

        // 2) xi = silu(causal_conv(xz[:, :DI]))
        conv_silu_kernel<<<(NTOK * DI + 255) / 256, 256>>>(
            p_xz, convw + (size_t)l * DI * 4, convb + (size_t)l * DI, p_xi, p_xibf);

        // 3) x_dbl = xi @ x_proj_w^T
        bgemm<2><<<dim3(1, NTOK / 128), 128>>>(
            p_xibf, p_xpwb + (size_t)l * 96 * DI, p_xdbl, p_xdblbf, nullptr,
            NTOK, 96, DI, DI, DI, 96);

        // 4) delta = softplus(x_dbl[:, :64] @ dt_w^T + dt_b)
        bgemm<1><<<dim3(DI / 128, NTOK / 128), 128>>>(
            p_xdblbf, p_dtwb + (size_t)l * DI * DR, p_delta, nullptr,
            dtb + (size_t)l * DI,
            NTOK, DI, DR, 96, DR, DI);

        // 5) chunked selective scan
        scanA<<<(NB * DI * NCH * 4) / 128, 128>>>(
            p_xdbl, p_delta, p_xi, Alog + (size_t)l * DI * DS,
            p_ypart, p_ap, p_he);
        scanB<<<(NB * DI * DS + 255) / 256, 256>>>(p_ap, p_he, p_h0);
        scanC<<<(NB * DI * NCH * 4) / 128, 128>>>(
            p_xdbl, p_delta, p_xi, p_xz,
            Alog + (size_t)l * DI * DS, Dv + (size_t)l * DI,
            p_ypart, p_h0, p_ybf);

        if (l < NL - 1) {
            // 6) tmp = y @ out_proj_w^T
            bgemm<0><<<dim3(DM / 128, NTOK / 128), 128>>>(
                p_ybf, p_outwb + (size_t)l * DM * DI, p_tmp, nullptr, nullptr,
                NTOK, DM, DI, DI, DI, DM);

            // 7) x = LN(tmp + x)
            ln_kernel<<<NTOK, 256>>>(p_tmp, p_x, p_xbf,
                                     lnw + (size_t)l * DM, lnb + (size_t)l * DM);
        } else {
            final_out_kernel<<<dim3(NB, DM / 256), 256>>>(
                p_ybf, p_outwb + (size_t)l * DM * DI, p_tmp4);
            final_ln_pred<<<NB, 256>>>(
                p_tmp4, p_x, lnw + (size_t)l * DM, lnb + (size_t)l * DM,
                predw, predb, out);
        }
    }
}

// round 14
// speedup vs baseline: 1.0629x; 1.0629x over previous
#include <cuda_runtime.h>
#include <cuda_bf16.h>
#include <math.h>
#include <stdint.h>

#define NL 6
#define NB 4
#define SEQ 2048
#define DM 1024
#define DI 2048
#define DS 16
#define DR 64
#define NTOK (NB*SEQ)   // 8192
#define NCH 16          // scan chunks per sequence
#define CL (SEQ/NCH)    // 128 steps per chunk

// ---------------- scratch (device globals; no allocations allowed) ----------
__device__ float g_x[NTOK*DM];
__device__ float g_xz[NTOK*2*DI];
__device__ float g_xi[NTOK*DI];
__device__ float g_xdbl[NTOK*96];
__device__ float g_delta[NTOK*DI];
__device__ float g_tmp[NTOK*DM];
__device__ float g_tmp4[NB*DM];
__device__ float g_ypart[NTOK*DI];
__device__ float g_ap[NB*DI*NCH*DS];
__device__ float g_he[NB*DI*NCH*DS];
__device__ float g_h0[NB*DI*NCH*DS];

__device__ __nv_bfloat16 g_xbf[NTOK*DM];
__device__ __nv_bfloat16 g_xibf[NTOK*DI];
__device__ __nv_bfloat16 g_ybf[NTOK*DI];
__device__ __nv_bfloat16 g_xdblbf[NTOK*96];
__device__ __nv_bfloat16 g_inw_bf[NL*2*DI*DM];
__device__ __nv_bfloat16 g_xpw_bf[NL*96*DI];
__device__ __nv_bfloat16 g_dtw_bf[NL*DI*DR];
__device__ __nv_bfloat16 g_outw_bf[NL*DM*DI];

// -------------------------- math helpers ------------------------------------
__device__ __forceinline__ float siluf(float x) { return x / (1.0f + __expf(-x)); }
// fast e^x (accurate for x <= 0), FMA-pipe only
__device__ __forceinline__ float fexp(float x) {
    float y = x * 1.4426950408889634f;
    float t = y + 12582912.0f;
    int   e = (__float_as_int(t) & 0x7FFFFF) - 0x400000;
    float f = y - (t - 12582912.0f);
    float p = 1.5403530e-4f;
    p = fmaf(p, f, 1.3333558e-3f);
    p = fmaf(p, f, 9.6181291e-3f);
    p = fmaf(p, f, 5.5504109e-2f);
    p = fmaf(p, f, 2.4022651e-1f);
    p = fmaf(p, f, 6.9314718e-1f);
    p = fmaf(p, f, 1.0f);
    if (e < -120) return 0.0f;
    return __int_as_float(__float_as_int(p) + (e << 23));
}
__device__ __forceinline__ float softp(float x) {
    return fmaxf(x, 0.0f) + log1pf(fexp(-fabsf(x)));
}
__device__ __forceinline__ uint32_t smem_u32(const void* p) {
    uint32_t a;
    asm("{ .reg .u64 t; cvta.to.shared.u64 t, %1; cvt.u32.u64 %0, t; }" : "=r"(a) : "l"(p));
    return a;
}
__device__ __forceinline__ void cp16(uint32_t dst, const void* src) {
    asm volatile("cp.async.cg.shared.global [%0], [%1], 16;" :: "r"(dst), "l"(src) : "memory");
}
__device__ __forceinline__ void mma_bf16(float* d, const uint32_t* a, const uint32_t* b) {
    asm volatile(
        "mma.sync.aligned.m16n8k16.row.col.f32.bf16.bf16.f32 "
        "{%0,%1,%2,%3}, {%4,%5,%6,%7}, {%8,%9}, {%0,%1,%2,%3};"
        : "+f"(d[0]), "+f"(d[1]), "+f"(d[2]), "+f"(d[3])
        : "r"(a[0]), "r"(a[1]), "r"(a[2]), "r"(a[3]), "r"(b[0]), "r"(b[1]));
}
__device__ __forceinline__ void ldsm4(uint32_t addr, uint32_t& r0, uint32_t& r1,
                                      uint32_t& r2, uint32_t& r3) {
    asm volatile("ldmatrix.sync.aligned.m8n8.x4.shared.b16 {%0,%1,%2,%3}, [%4];"
                 : "=r"(r0), "=r"(r1), "=r"(r2), "=r"(r3) : "r"(addr));
}

// ---------------------------------------------------------------------------
// bf16 mma.sync GEMM:  C[M,N] = A[M,K] * B[N,K]^T   (both bf16, K-contiguous)
// 128x128 CTA tile, BK=32, 256 threads (8 warps 4x2, 32x64 warp tiles),
// THREE-stage cp.async pipeline (dynamic smem, 61.4KB), ONE sync per K-iter,
// ldmatrix.x4 fragment loads, __launch_bounds__(256,2).
// Rows padded to 40 halves (80B) => conflict-free LDSM phases.
// MODE 0: fp32 store.  MODE 1: softplus(acc+bias).  MODE 2: fp32 + bf16 copy.
// ---------------------------------------------------------------------------
#define GLDS 40                         // halves per row (80B stride)
#define GASZ (128 * GLDS * 2)           // bytes per A tile stage = 10240
#define GSTG (2 * GASZ)                 // bytes per stage (A + B) = 20480
#define GSMEM (3 * GSTG)                // 61440 bytes total

template<int MODE>
__global__ __launch_bounds__(256, 2) void bgemm(
    const __nv_bfloat16* __restrict__ A, const __nv_bfloat16* __restrict__ Bw,
    float* __restrict__ C, __nv_bfloat16* __restrict__ Cb,
    const float* __restrict__ bias,
    int M, int N, int K, int lda, int ldb, int ldc)
{
    constexpr int BK = 32;
    constexpr int MT = 2, NT = 8;           // warp tile 32x64

    extern __shared__ __nv_bfloat16 dsmem[];
    const uint32_t sbase = smem_u32(dsmem);

    const int tid = threadIdx.x, lane = tid & 31, warp = tid >> 5;
    const int m0 = blockIdx.y * 128, n0 = blockIdx.x * 128;
    const int wm = (warp >> 1) * 32, wn = (warp & 1) * 64;
    const int grp = lane >> 2, thr = lane & 3;

    // ldmatrix source coordinates (within tile)
    const int a_row = wm + (lane & 15);                      // + mt*16
    const int a_col = (lane >> 4) * 8;                       // + kk
    const int b_row = wn + (lane & 7) + ((lane >> 4) << 3);  // + np*16
    const int b_col = ((lane >> 3) & 1) * 8;                 // + kk

    float acc[MT][NT][4];
#pragma unroll
    for (int i = 0; i < MT; i++)
#pragma unroll
        for (int j = 0; j < NT; j++)
#pragma unroll
            for (int q = 0; q < 4; q++) acc[i][j][q] = 0.0f;

    auto stage = [&](int kt, int s) {
        int k0 = kt << 5;
        uint32_t ab = sbase + s * GSTG;
        uint32_t bb = ab + GASZ;
#pragma unroll
        for (int i = 0; i < 2; i++) {
            int idx = tid + (i << 8);
            int r = idx >> 2, c = idx & 3;
            cp16(ab + (uint32_t)(r * (GLDS * 2) + c * 16),
                 A + (size_t)(m0 + r) * lda + k0 + c * 8);
        }
#pragma unroll
        for (int i = 0; i < 2; i++) {
            int idx = tid + (i << 8);
            int r = idx >> 2, c = idx & 3;
            int gr = n0 + r; if (gr >= N) gr = N - 1;
            cp16(bb + (uint32_t)(r * (GLDS * 2) + c * 16),
                 Bw + (size_t)gr * ldb + k0 + c * 8);
        }
        asm volatile("cp.async.commit_group;" ::: "memory");
    };

    auto comp = [&](int s) {
        uint32_t ab = sbase + s * GSTG;
        uint32_t bb = ab + GASZ;
#pragma unroll
        for (int kk = 0; kk < BK; kk += 16) {
            uint32_t af[MT][4], bf[NT][2];
#pragma unroll
            for (int mt = 0; mt < MT; mt++)
                ldsm4(ab + (uint32_t)(((a_row + mt * 16) * GLDS + kk + a_col) * 2),
                      af[mt][0], af[mt][1], af[mt][2], af[mt][3]);
#pragma unroll
            for (int np = 0; np < NT / 2; np++)
                ldsm4(bb + (uint32_t)(((b_row + np * 16) * GLDS + kk + b_col) * 2),
                      bf[2 * np][0], bf[2 * np][1], bf[2 * np + 1][0], bf[2 * np + 1][1]);
#pragma unroll
            for (int mt = 0; mt < MT; mt++)
#pragma unroll
                for (int nt = 0; nt < NT; nt++)
                    mma_bf16(acc[mt][nt], af[mt], bf[nt]);
        }
    };

    const int NC = K >> 5;   // K >= 64 always => NC >= 2
    stage(0, 0);
    stage(1, 1);
    for (int kt = 0; kt < NC; kt++) {
        if (kt + 1 < NC)
            asm volatile("cp.async.wait_group 1;" ::: "memory");
        else
            asm volatile("cp.async.wait_group 0;" ::: "memory");
        __syncthreads();
        comp(kt % 3);
        if (kt + 2 < NC) stage(kt + 2, (kt + 2) % 3);
    }

#pragma unroll
    for (int mt = 0; mt < MT; mt++) {
        int r0 = m0 + wm + mt * 16 + grp;
#pragma unroll
        for (int nt = 0; nt < NT; nt++) {
            int c0 = n0 + wn + nt * 8 + thr * 2;
            if (c0 < N) {
                float v0 = acc[mt][nt][0], v1 = acc[mt][nt][1];
                float v2 = acc[mt][nt][2], v3 = acc[mt][nt][3];
                if (MODE == 1) {
                    float b0 = bias[c0], b1 = bias[c0 + 1];
                    v0 = softp(v0 + b0); v1 = softp(v1 + b1);
                    v2 = softp(v2 + b0); v3 = softp(v3 + b1);
                }
                *(float2*)&C[(size_t)r0 * ldc + c0]       = make_float2(v0, v1);
                *(float2*)&C[(size_t)(r0 + 8) * ldc + c0] = make_float2(v2, v3);
                if (MODE == 2) {
                    __nv_bfloat162 h0, h1;
                    h0.x = __float2bfloat16(v0); h0.y = __float2bfloat16(v1);
                    h1.x = __float2bfloat16(v2); h1.y = __float2bfloat16(v3);
                    *(__nv_bfloat162*)&Cb[(size_t)r0 * ldc + c0]       = h0;
                    *(__nv_bfloat162*)&Cb[(size_t)(r0 + 8) * ldc + c0] = h1;
                }
            }
        }
    }
}

// ---------------------------------------------------------------------------
__global__ void f2bf_all(const float* __restrict__ s1, const float* __restrict__ s2,
                         const float* __restrict__ s3, const float* __restrict__ s4,
                         __nv_bfloat16* __restrict__ d1, __nv_bfloat16* __restrict__ d2,
                         __nv_bfloat16* __restrict__ d3, __nv_bfloat16* __restrict__ d4,
                         int n1, int n2, int n3, int n4)
{
    int i = blockIdx.x * blockDim.x + threadIdx.x;
    if (i < n1) { d1[i] = __float2bfloat16(s1[i]); return; }
    i -= n1;
    if (i < n2) { d2[i] = __float2bfloat16(s2[i]); return; }
    i -= n2;
    if (i < n3) { d3[i] = __float2bfloat16(s3[i]); return; }
    i -= n3;
    if (i < n4) d4[i] = __float2bfloat16(s4[i]);
}
__global__ void copy_kernel(const float* __restrict__ src, float* __restrict__ dst,
                            __nv_bfloat16* __restrict__ dstb, int n)
{
    int i = blockIdx.x * blockDim.x + threadIdx.x;
    if (i < n) { float v = src[i]; dst[i] = v; dstb[i] = __float2bfloat16(v); }
}

// Causal depthwise conv (width 4) + bias + SiLU; fp32 + bf16 outputs.
__global__ void conv_silu_kernel(const float* __restrict__ xz,
                                 const float* __restrict__ cw,
                                 const float* __restrict__ cb,
                                 float* __restrict__ xi,
                                 __nv_bfloat16* __restrict__ xib)
{
    int idx = blockIdx.x * blockDim.x + threadIdx.x;
    if (idx >= NTOK * DI) return;
    int d = idx % DI;
    int n = idx / DI;
    int t = n % SEQ;
    float acc = cb[d];
#pragma unroll
    for (int k = 0; k < 4; k++) {
        int tt = t - 3 + k;
        if (tt >= 0)
            acc = fmaf(cw[d * 4 + k], xz[(size_t)(n - 3 + k) * (2 * DI) + d], acc);
    }
    float v = siluf(acc);
    xi[idx] = v;
    xib[idx] = __float2bfloat16(v);
}

// ---------------------------------------------------------------------------
// Chunked selective scan (validated R11 structure).
// ---------------------------------------------------------------------------
__device__ __forceinline__ void scan_coeffs(
    const float* A_log, int d, int sub, float* Av, bool& trick)
{
#pragma unroll
    for (int i = 0; i < 4; i++)
        Av[i] = -__expf(A_log[d * DS + sub * 4 + i]);
    int e0 = sub * 4 + 1;
    trick = true;
#pragma unroll
    for (int i = 0; i < 4; i++)
        trick = trick && (fabsf(Av[i] + (float)(e0 + i)) < 3e-4f * (float)(e0 + i));
}
__device__ __forceinline__ void scan_dA(bool trick, const float* Av, int sub,
                                        float dlt, float* a)
{
    if (trick) {
        float r = fexp(-dlt);
        float r2 = r * r, r4 = r2 * r2;
        float p = r;
        if (sub & 1) p *= r4;
        if (sub & 2) p *= r4 * r4;
        a[0] = p; a[1] = p * r; a[2] = a[1] * r; a[3] = a[2] * r;
    } else {
        a[0] = fexp(dlt * Av[0]); a[1] = fexp(dlt * Av[1]);
        a[2] = fexp(dlt * Av[2]); a[3] = fexp(dlt * Av[3]);
    }
}

__global__ __launch_bounds__(128) void scanA(
    const float* __restrict__ xdbl, const float* __restrict__ delta,
    const float* __restrict__ xi, const float* __restrict__ A_log,
    float* __restrict__ ypart, float* __restrict__ apv, float* __restrict__ hev)
{
    int gt  = blockIdx.x * 128 + threadIdx.x;
    int sub = gt & 3;
    int ch  = gt >> 2;                 // (b*DI+d)*NCH + c
    if (ch >= NB * DI * NCH) return;
    int c  = ch % NCH;
    int bd = ch / NCH;
    int d  = bd % DI, b = bd / DI;

    float Av[4]; bool trick;
    scan_coeffs(A_log, d, sub, Av, trick);

    float h[4] = {0.f, 0.f, 0.f, 0.f};
    float ap[4] = {1.f, 1.f, 1.f, 1.f};
    const int base = b * SEQ + c * CL;

    for (int t = 0; t < CL; t++) {
        int n = base + t;
        float dlt = __ldg(&delta[(size_t)n * DI + d]);
        float u   = __ldg(&xi[(size_t)n * DI + d]);
        float4 Bv = __ldg((const float4*)(xdbl + (size_t)n * 96 + 64 + sub * 4));
        float4 Cv = __ldg((const float4*)(xdbl + (size_t)n * 96 + 80 + sub * 4));
        float a[4];
        scan_dA(trick, Av, sub, dlt, a);
        float du = dlt * u;
#pragma unroll
        for (int i = 0; i < 4; i++) ap[i] *= a[i];
        h[0] = fmaf(a[0], h[0], Bv.x * du);
        h[1] = fmaf(a[1], h[1], Bv.y * du);
        h[2] = fmaf(a[2], h[2], Bv.z * du);
        h[3] = fmaf(a[3], h[3], Bv.w * du);
        float yp = h[0] * Cv.x;
        yp = fmaf(h[1], Cv.y, yp);
        yp = fmaf(h[2], Cv.z, yp);
        yp = fmaf(h[3], Cv.w, yp);
        yp += __shfl_xor_sync(0xffffffffu, yp, 1);
        yp += __shfl_xor_sync(0xffffffffu, yp, 2);
        if (sub == 0) ypart[(size_t)n * DI + d] = yp;
    }
#pragma unroll
    for (int i = 0; i < 4; i++) {
        apv[ch * 16 + sub * 4 + i] = ap[i];
        hev[ch * 16 + sub * 4 + i] = h[i];
    }
}

__global__ void scanB(const float* __restrict__ apv, const float* __restrict__ hev,
                      float* __restrict__ h0v)
{
    int i = blockIdx.x * 256 + threadIdx.x;   // over NB*DI*DS
    if (i >= NB * DI * DS) return;
    int s  = i & 15;
    int bd = i >> 4;
    float h = 0.0f;
#pragma unroll
    for (int c = 0; c < NCH; c++) {
        int idx = (bd * NCH + c) * 16 + s;
        h0v[idx] = h;
        h = fmaf(apv[idx], h, hev[idx]);
    }
}

__global__ __launch_bounds__(128) void scanC(
    const float* __restrict__ xdbl, const float* __restrict__ delta,
    const float* __restrict__ xi, const float* __restrict__ xz,
    const float* __restrict__ A_log, const float* __restrict__ Dv,
    const float* __restrict__ ypart, const float* __restrict__ h0v,
    __nv_bfloat16* __restrict__ ybf)
{
    int gt  = blockIdx.x * 128 + threadIdx.x;
    int sub = gt & 3;
    int ch  = gt >> 2;
    if (ch >= NB * DI * NCH) return;
    int c  = ch % NCH;
    int bd = ch / NCH;
    int d  = bd % DI, b = bd / DI;

    float Av[4]; bool trick;
    scan_coeffs(A_log, d, sub, Av, trick);
    float Dd = Dv[d];

    float h0[4], P[4] = {1.f, 1.f, 1.f, 1.f};
#pragma unroll
    for (int i = 0; i < 4; i++) h0[i] = h0v[ch * 16 + sub * 4 + i];

    const int base = b * SEQ + c * CL;
    for (int t = 0; t < CL; t++) {
        int n = base + t;
        float dlt = __ldg(&delta[(size_t)n * DI + d]);
        float4 Cv = __ldg((const float4*)(xdbl + (size_t)n * 96 + 80 + sub * 4));
        float a[4];
        scan_dA(trick, Av, sub, dlt, a);
#pragma unroll
        for (int i = 0; i < 4; i++) P[i] *= a[i];
        float corr = (P[0] * h0[0]) * Cv.x;
        corr = fmaf(P[1] * h0[1], Cv.y, corr);
        corr = fmaf(P[2] * h0[2], Cv.z, corr);
        corr = fmaf(P[3] * h0[3], Cv.w, corr);
        corr += __shfl_xor_sync(0xffffffffu, corr, 1);
        corr += __shfl_xor_sync(0xffffffffu, corr, 2);
        if (sub == 0) {
            float y = ypart[(size_t)n * DI + d] + corr;
            float u = __ldg(&xi[(size_t)n * DI + d]);
            float zv = __ldg(&xz[(size_t)n * (2 * DI) + DI + d]);
            ybf[(size_t)n * DI + d] = __float2bfloat16((y + u * Dd) * siluf(zv));
        }
    }
}

// LayerNorm with fused residual: x = LN(tmp + x)*w + b; fp32 + bf16 outputs.
__global__ __launch_bounds__(256) void ln_kernel(
    const float* __restrict__ tmp, float* __restrict__ x,
    __nv_bfloat16* __restrict__ xb,
    const float* __restrict__ w, const float* __restrict__ bb)
{
    int n = blockIdx.x;
    int tid = threadIdx.x;
    __shared__ float sred[40];

    float v[4];
    float s = 0.0f;
#pragma unroll
    for (int i = 0; i < 4; i++) {
        int c = tid + 256 * i;
        v[i] = tmp[(size_t)n * DM + c] + x[(size_t)n * DM + c];
        s += v[i];
    }
    for (int o = 16; o; o >>= 1) s += __shfl_xor_sync(0xffffffffu, s, o);
    if ((tid & 31) == 0) sred[tid >> 5] = s;
    __syncthreads();
    if (tid < 8) {
        s = sred[tid];
        for (int o = 4; o; o >>= 1) s += __shfl_xor_sync(0xffu, s, o);
        if (tid == 0) sred[32] = s;
    }
    __syncthreads();
    float mu = sred[32] * (1.0f / DM);

    float s2 = 0.0f;
#pragma unroll
    for (int i = 0; i < 4; i++) {
        float dv = v[i] - mu;
        s2 += dv * dv;
    }
    for (int o = 16; o; o >>= 1) s2 += __shfl_xor_sync(0xffffffffu, s2, o);
    if ((tid & 31) == 0) sred[tid >> 5] = s2;
    __syncthreads();
    if (tid < 8) {
        s2 = sred[tid];
        for (int o = 4; o; o >>= 1) s2 += __shfl_xor_sync(0xffu, s2, o);
        if (tid == 0) sred[33] = s2;
    }
    __syncthreads();
    float inv = rsqrtf(sred[33] * (1.0f / DM) + 1e-5f);

#pragma unroll
    for (int i = 0; i < 4; i++) {
        int c = tid + 256 * i;
        float o = (v[i] - mu) * inv * w[c] + bb[c];
        x[(size_t)n * DM + c] = o;
        xb[(size_t)n * DM + c] = __float2bfloat16(o);
    }
}

// Layer-6 shortcut: out_proj restricted to last token of each batch.
__global__ __launch_bounds__(256) void final_out_kernel(
    const __nv_bfloat16* __restrict__ y, const __nv_bfloat16* __restrict__ outw,
    float* __restrict__ tmp4)
{
    int b = blockIdx.x, col = blockIdx.y * 256 + threadIdx.x;
    const __nv_bfloat16* yr = y + (size_t)(b * SEQ + SEQ - 1) * DI;
    const __nv_bfloat16* wr = outw + (size_t)col * DI;
    __shared__ __nv_bfloat16 ys[DI];
    for (int i = threadIdx.x; i < DI; i += 256) ys[i] = yr[i];
    __syncthreads();
    float s = 0.0f;
#pragma unroll 4
    for (int k = 0; k < DI; k += 8) {
        uint4 wv = *(const uint4*)(wr + k);
        const __nv_bfloat162* w2 = (const __nv_bfloat162*)&wv;
        const __nv_bfloat162* y2 = (const __nv_bfloat162*)&ys[k];
#pragma unroll
        for (int j = 0; j < 4; j++) {
            s = fmaf(__bfloat162float(y2[j].x), __bfloat162float(w2[j].x), s);
            s = fmaf(__bfloat162float(y2[j].y), __bfloat162float(w2[j].y), s);
        }
    }
    tmp4[b * DM + col] = s;
}

// Layer-6 LN + prediction fused, last tokens only.
__global__ __launch_bounds__(256) void final_ln_pred(
    const float* __restrict__ tmp4, const float* __restrict__ x,
    const float* __restrict__ w, const float* __restrict__ bb,
    const float* __restrict__ pw, const float* __restrict__ pb,
    float* __restrict__ out)
{
    int b = blockIdx.x;
    int tid = threadIdx.x;
    __shared__ float sred[40];
    const float* row = x + (size_t)(b * SEQ + SEQ - 1) * DM;

    float v[4];
    float s = 0.0f;
#pragma unroll
    for (int i = 0; i < 4; i++) {
        int c = tid + 256 * i;
        v[i] = tmp4[b * DM + c] + row[c];
        s += v[i];
    }
    for (int o = 16; o; o >>= 1) s += __shfl_xor_sync(0xffffffffu, s, o);
    if ((tid & 31) == 0) sred[tid >> 5] = s;
    __syncthreads();
    if (tid < 8) {
        s = sred[tid];
        for (int o = 4; o; o >>= 1) s += __shfl_xor_sync(0xffu, s, o);
        if (tid == 0) sred[32] = s;
    }
    __syncthreads();
    float mu = sred[32] * (1.0f / DM);

    float s2 = 0.0f;
#pragma unroll
    for (int i = 0; i < 4; i++) { float dv = v[i] - mu; s2 += dv * dv; }
    for (int o = 16; o; o >>= 1) s2 += __shfl_xor_sync(0xffffffffu, s2, o);
    if ((tid & 31) == 0) sred[tid >> 5] = s2;
    __syncthreads();
    if (tid < 8) {
        s2 = sred[tid];
        for (int o = 4; o; o >>= 1) s2 += __shfl_xor_sync(0xffu, s2, o);
        if (tid == 0) sred[33] = s2;
    }
    __syncthreads();
    float inv = rsqrtf(sred[33] * (1.0f / DM) + 1e-5f);

    float s3 = 0.0f;
#pragma unroll
    for (int i = 0; i < 4; i++) {
        int c = tid + 256 * i;
        float o = (v[i] - mu) * inv * w[c] + bb[c];
        s3 = fmaf(o, pw[c], s3);
    }
    for (int o = 16; o; o >>= 1) s3 += __shfl_xor_sync(0xffffffffu, s3, o);
    if ((tid & 31) == 0) sred[tid >> 5] = s3;
    __syncthreads();
    if (tid < 8) {
        s3 = sred[tid];
        for (int o = 4; o; o >>= 1) s3 += __shfl_xor_sync(0xffu, s3, o);
        if (tid == 0) out[b] = s3 + pb[0];
    }
}

// ---------------------------------------------------------------------------
extern "C" void kernel_launch(void* const* d_in, const int* in_sizes, int n_in,
                              void* d_out, int out_size)
{
    const float* x_in  = (const float*)d_in[0];
    const float* inw   = (const float*)d_in[1];
    const float* convw = (const float*)d_in[2];
    const float* convb = (const float*)d_in[3];
    const float* xpw   = (const float*)d_in[4];
    const float* dtw   = (const float*)d_in[5];
    const float* dtb   = (const float*)d_in[6];
    const float* Alog  = (const float*)d_in[7];
    const float* Dv    = (const float*)d_in[8];
    const float* outw  = (const float*)d_in[9];
    const float* lnw   = (const float*)d_in[10];
    const float* lnb   = (const float*)d_in[11];
    const float* predw = (const float*)d_in[12];
    const float* predb = (const float*)d_in[13];
    float* out = (float*)d_out;

    float *p_x, *p_xz, *p_xi, *p_xdbl, *p_delta, *p_tmp, *p_tmp4;
    float *p_ypart, *p_ap, *p_he, *p_h0;
    __nv_bfloat16 *p_xbf, *p_xibf, *p_ybf, *p_xdblbf;
    __nv_bfloat16 *p_inwb, *p_xpwb, *p_dtwb, *p_outwb;
    cudaGetSymbolAddress((void**)&p_x, g_x);
    cudaGetSymbolAddress((void**)&p_xz, g_xz);
    cudaGetSymbolAddress((void**)&p_xi, g_xi);
    cudaGetSymbolAddress((void**)&p_xdbl, g_xdbl);
    cudaGetSymbolAddress((void**)&p_delta, g_delta);
    cudaGetSymbolAddress((void**)&p_tmp, g_tmp);
    cudaGetSymbolAddress((void**)&p_tmp4, g_tmp4);
    cudaGetSymbolAddress((void**)&p_ypart, g_ypart);
    cudaGetSymbolAddress((void**)&p_ap, g_ap);
    cudaGetSymbolAddress((void**)&p_he, g_he);
    cudaGetSymbolAddress((void**)&p_h0, g_h0);
    cudaGetSymbolAddress((void**)&p_xbf, g_xbf);
    cudaGetSymbolAddress((void**)&p_xibf, g_xibf);
    cudaGetSymbolAddress((void**)&p_ybf, g_ybf);
    cudaGetSymbolAddress((void**)&p_xdblbf, g_xdblbf);
    cudaGetSymbolAddress((void**)&p_inwb, g_inw_bf);
    cudaGetSymbolAddress((void**)&p_xpwb, g_xpw_bf);
    cudaGetSymbolAddress((void**)&p_dtwb, g_dtw_bf);
    cudaGetSymbolAddress((void**)&p_outwb, g_outw_bf);

    // Allow 60KB dynamic smem for the 3-stage GEMM (idempotent; host-side only)
    cudaFuncSetAttribute(bgemm<0>, cudaFuncAttributeMaxDynamicSharedMemorySize, GSMEM);
    cudaFuncSetAttribute(bgemm<1>, cudaFuncAttributeMaxDynamicSharedMemorySize, GSMEM);
    cudaFuncSetAttribute(bgemm<2>, cudaFuncAttributeMaxDynamicSharedMemorySize, GSMEM);

    // One launch for all weight conversions
    {
        int n1 = NL * 2 * DI * DM, n2 = NL * 96 * DI, n3 = NL * DI * DR, n4 = NL * DM * DI;
        int nt = n1 + n2 + n3 + n4;
        f2bf_all<<<(nt + 255) / 256, 256>>>(inw, xpw, dtw, outw,
                                            p_inwb, p_xpwb, p_dtwb, p_outwb,
                                            n1, n2, n3, n4);
    }
    copy_kernel<<<(NTOK * DM + 255) / 256, 256>>>(x_in, p_x, p_xbf, NTOK * DM);

    for (int l = 0; l < NL; l++) {
        // 1) xz = x @ in_proj_w^T
        bgemm<0><<<dim3((2 * DI) / 128, NTOK / 128), 256, GSMEM>>>(
            p_xbf, p_inwb + (size_t)l * 2 * DI * DM, p_xz, nullptr, nullptr,
            NTOK, 2 * DI, DM, DM, DM, 2 * DI);

        // 2) xi = silu(causal_conv(xz[:, :DI]))
        conv_silu_kernel<<<(NTOK * DI + 255) / 256, 256>>>(
            p_xz, convw + (size_t)l * DI * 4, convb + (size_t)l * DI, p_xi, p_xibf);

        // 3) x_dbl = xi @ x_proj_w^T
        bgemm<2><<<dim3(1, NTOK / 128), 256, GSMEM>>>(
            p_xibf, p_xpwb + (size_t)l * 96 * DI, p_xdbl, p_xdblbf, nullptr,
            NTOK, 96, DI, DI, DI, 96);

        // 4) delta = softplus(x_dbl[:, :64] @ dt_w^T + dt_b)
        bgemm<1><<<dim3(DI / 128, NTOK / 128), 256, GSMEM>>>(
            p_xdblbf, p_dtwb + (size_t)l * DI * DR, p_delta, nullptr,
            dtb + (size_t)l * DI,
            NTOK, DI, DR, 96, DR, DI);

        // 5) chunked selective scan
        scanA<<<(NB * DI * NCH * 4) / 128, 128>>>(
            p_xdbl, p_delta, p_xi, Alog + (size_t)l * DI * DS,
            p_ypart, p_ap, p_he);
        scanB<<<(NB * DI * DS + 255) / 256, 256>>>(p_ap, p_he, p_h0);
        scanC<<<(NB * DI * NCH * 4) / 128, 128>>>(
            p_xdbl, p_delta, p_xi, p_xz,
            Alog + (size_t)l * DI * DS, Dv + (size_t)l * DI,
            p_ypart, p_h0, p_ybf);

        if (l < NL - 1) {
            // 6) tmp = y @ out_proj_w^T
            bgemm<0><<<dim3(DM / 128, NTOK / 128), 256, GSMEM>>>(
                p_ybf, p_outwb + (size_t)l * DM * DI, p_tmp, nullptr, nullptr,
                NTOK, DM, DI, DI, DI, DM);

            // 7) x = LN(tmp + x)
            ln_kernel<<<NTOK, 256>>>(p_tmp, p_x, p_xbf,
                                     lnw + (size_t)l * DM, lnb + (size_t)l * DM);
        } else {
            final_out_kernel<<<dim3(NB, DM / 256), 256>>>(
                p_ybf, p_outwb + (size_t)l * DM * DI, p_tmp4);
            final_ln_pred<<<NB, 256>>>(
                p_tmp4, p_x, lnw + (size_t)l * DM, lnb + (size_t)l * DM,
                predw, predb, out);
        }
    }
}

// round 15
// speedup vs baseline: 1.1579x; 1.0895x over previous
#include <cuda_runtime.h>
#include <cuda_bf16.h>
#include <math.h>
#include <stdint.h>

#define NL 6
#define NB 4
#define SEQ 2048
#define DM 1024
#define DI 2048
#define DS 16
#define DR 64
#define NTOK (NB*SEQ)   // 8192
#define NCH 16          // scan chunks per sequence
#define CL (SEQ/NCH)    // 128 steps per chunk
#define XPK 4           // split-K factor for x_proj

// ---------------- scratch (device globals; no allocations allowed) ----------
__device__ float g_x[NTOK*DM];
__device__ float g_xz[NTOK*2*DI];
__device__ float g_xi[NTOK*DI];
__device__ float g_xdbl[NTOK*96];
__device__ float g_xdp[XPK*NTOK*96];
__device__ float g_delta[NTOK*DI];
__device__ float g_tmp[NTOK*DM];
__device__ float g_tmp4[NB*DM];
__device__ float g_ap[NB*DI*NCH*DS];
__device__ float g_he[NB*DI*NCH*DS];
__device__ float g_h0[NB*DI*NCH*DS];

__device__ __nv_bfloat16 g_ypbf[NTOK*DI];
__device__ __nv_bfloat16 g_xbf[NTOK*DM];
__device__ __nv_bfloat16 g_xibf[NTOK*DI];
__device__ __nv_bfloat16 g_ybf[NTOK*DI];
__device__ __nv_bfloat16 g_xdblbf[NTOK*96];
__device__ __nv_bfloat16 g_inw_bf[NL*2*DI*DM];
__device__ __nv_bfloat16 g_xpw_bf[NL*96*DI];
__device__ __nv_bfloat16 g_dtw_bf[NL*DI*DR];
__device__ __nv_bfloat16 g_outw_bf[NL*DM*DI];

// -------------------------- math helpers ------------------------------------
__device__ __forceinline__ float siluf(float x) { return x / (1.0f + __expf(-x)); }
__device__ __forceinline__ float fexp(float x) {
    float y = x * 1.4426950408889634f;
    float t = y + 12582912.0f;
    int   e = (__float_as_int(t) & 0x7FFFFF) - 0x400000;
    float f = y - (t - 12582912.0f);
    float p = 1.5403530e-4f;
    p = fmaf(p, f, 1.3333558e-3f);
    p = fmaf(p, f, 9.6181291e-3f);
    p = fmaf(p, f, 5.5504109e-2f);
    p = fmaf(p, f, 2.4022651e-1f);
    p = fmaf(p, f, 6.9314718e-1f);
    p = fmaf(p, f, 1.0f);
    if (e < -120) return 0.0f;
    return __int_as_float(__float_as_int(p) + (e << 23));
}
__device__ __forceinline__ float softp(float x) {
    return fmaxf(x, 0.0f) + log1pf(fexp(-fabsf(x)));
}
__device__ __forceinline__ uint32_t smem_u32(const void* p) {
    uint32_t a;
    asm("{ .reg .u64 t; cvta.to.shared.u64 t, %1; cvt.u32.u64 %0, t; }" : "=r"(a) : "l"(p));
    return a;
}
__device__ __forceinline__ void cp16(uint32_t dst, const void* src) {
    asm volatile("cp.async.cg.shared.global [%0], [%1], 16;" :: "r"(dst), "l"(src) : "memory");
}
__device__ __forceinline__ void mma_bf16(float* d, const uint32_t* a, const uint32_t* b) {
    asm volatile(
        "mma.sync.aligned.m16n8k16.row.col.f32.bf16.bf16.f32 "
        "{%0,%1,%2,%3}, {%4,%5,%6,%7}, {%8,%9}, {%0,%1,%2,%3};"
        : "+f"(d[0]), "+f"(d[1]), "+f"(d[2]), "+f"(d[3])
        : "r"(a[0]), "r"(a[1]), "r"(a[2]), "r"(a[3]), "r"(b[0]), "r"(b[1]));
}
__device__ __forceinline__ void ldsm4(uint32_t addr, uint32_t& r0, uint32_t& r1,
                                      uint32_t& r2, uint32_t& r3) {
    asm volatile("ldmatrix.sync.aligned.m8n8.x4.shared.b16 {%0,%1,%2,%3}, [%4];"
                 : "=r"(r0), "=r"(r1), "=r"(r2), "=r"(r3) : "r"(addr));
}

// ---------------------------------------------------------------------------
// bf16 mma.sync GEMM (winning R14 config): 128x128 CTA tile, BK=32, 8 warps,
// 3-stage cp.async pipeline, one sync per K-iter, ldmatrix.x4.
// MODE 0: fp32 store.  MODE 1: softplus(acc+bias).  MODE 2: fp32 + bf16 copy.
// SPLITK 1: blockIdx.z selects K-slice of length K; partials at C + z*M*ldc.
// ---------------------------------------------------------------------------
#define GLDS 40
#define GASZ (128 * GLDS * 2)
#define GSTG (2 * GASZ)
#define GSMEM (3 * GSTG)

template<int MODE, int SPLITK>
__global__ __launch_bounds__(256, 2) void bgemm(
    const __nv_bfloat16* __restrict__ A, const __nv_bfloat16* __restrict__ Bw,
    float* __restrict__ C, __nv_bfloat16* __restrict__ Cb,
    const float* __restrict__ bias,
    int M, int N, int K, int lda, int ldb, int ldc)
{
    constexpr int BK = 32;
    constexpr int MT = 2, NT = 8;

    extern __shared__ __nv_bfloat16 dsmem[];
    const uint32_t sbase = smem_u32(dsmem);

    if (SPLITK) {
        size_t ko = (size_t)blockIdx.z * K;
        A += ko; Bw += ko;
        C += (size_t)blockIdx.z * M * ldc;
    }

    const int tid = threadIdx.x, lane = tid & 31, warp = tid >> 5;
    const int m0 = blockIdx.y * 128, n0 = blockIdx.x * 128;
    const int wm = (warp >> 1) * 32, wn = (warp & 1) * 64;
    const int grp = lane >> 2, thr = lane & 3;

    const int a_row = wm + (lane & 15);
    const int a_col = (lane >> 4) * 8;
    const int b_row = wn + (lane & 7) + ((lane >> 4) << 3);
    const int b_col = ((lane >> 3) & 1) * 8;

    float acc[MT][NT][4];
#pragma unroll
    for (int i = 0; i < MT; i++)
#pragma unroll
        for (int j = 0; j < NT; j++)
#pragma unroll
            for (int q = 0; q < 4; q++) acc[i][j][q] = 0.0f;

    auto stage = [&](int kt, int s) {
        int k0 = kt << 5;
        uint32_t ab = sbase + s * GSTG;
        uint32_t bb = ab + GASZ;
#pragma unroll
        for (int i = 0; i < 2; i++) {
            int idx = tid + (i << 8);
            int r = idx >> 2, c = idx & 3;
            cp16(ab + (uint32_t)(r * (GLDS * 2) + c * 16),
                 A + (size_t)(m0 + r) * lda + k0 + c * 8);
        }
#pragma unroll
        for (int i = 0; i < 2; i++) {
            int idx = tid + (i << 8);
            int r = idx >> 2, c = idx & 3;
            int gr = n0 + r; if (gr >= N) gr = N - 1;
            cp16(bb + (uint32_t)(r * (GLDS * 2) + c * 16),
                 Bw + (size_t)gr * ldb + k0 + c * 8);
        }
        asm volatile("cp.async.commit_group;" ::: "memory");
    };

    auto comp = [&](int s) {
        uint32_t ab = sbase + s * GSTG;
        uint32_t bb = ab + GASZ;
#pragma unroll
        for (int kk = 0; kk < BK; kk += 16) {
            uint32_t af[MT][4], bf[NT][2];
#pragma unroll
            for (int mt = 0; mt < MT; mt++)
                ldsm4(ab + (uint32_t)(((a_row + mt * 16) * GLDS + kk + a_col) * 2),
                      af[mt][0], af[mt][1], af[mt][2], af[mt][3]);
#pragma unroll
            for (int np = 0; np < NT / 2; np++)
                ldsm4(bb + (uint32_t)(((b_row + np * 16) * GLDS + kk + b_col) * 2),
                      bf[2 * np][0], bf[2 * np][1], bf[2 * np + 1][0], bf[2 * np + 1][1]);
#pragma unroll
            for (int mt = 0; mt < MT; mt++)
#pragma unroll
                for (int nt = 0; nt < NT; nt++)
                    mma_bf16(acc[mt][nt], af[mt], bf[nt]);
        }
    };

    const int NC = K >> 5;
    stage(0, 0);
    stage(1, 1);
    for (int kt = 0; kt < NC; kt++) {
        if (kt + 1 < NC)
            asm volatile("cp.async.wait_group 1;" ::: "memory");
        else
            asm volatile("cp.async.wait_group 0;" ::: "memory");
        __syncthreads();
        comp(kt % 3);
        if (kt + 2 < NC) stage(kt + 2, (kt + 2) % 3);
    }

#pragma unroll
    for (int mt = 0; mt < MT; mt++) {
        int r0 = m0 + wm + mt * 16 + grp;
#pragma unroll
        for (int nt = 0; nt < NT; nt++) {
            int c0 = n0 + wn + nt * 8 + thr * 2;
            if (c0 < N) {
                float v0 = acc[mt][nt][0], v1 = acc[mt][nt][1];
                float v2 = acc[mt][nt][2], v3 = acc[mt][nt][3];
                if (MODE == 1) {
                    float b0 = bias[c0], b1 = bias[c0 + 1];
                    v0 = softp(v0 + b0); v1 = softp(v1 + b1);
                    v2 = softp(v2 + b0); v3 = softp(v3 + b1);
                }
                *(float2*)&C[(size_t)r0 * ldc + c0]       = make_float2(v0, v1);
                *(float2*)&C[(size_t)(r0 + 8) * ldc + c0] = make_float2(v2, v3);
                if (MODE == 2) {
                    __nv_bfloat162 h0, h1;
                    h0.x = __float2bfloat16(v0); h0.y = __float2bfloat16(v1);
                    h1.x = __float2bfloat16(v2); h1.y = __float2bfloat16(v3);
                    *(__nv_bfloat162*)&Cb[(size_t)r0 * ldc + c0]       = h0;
                    *(__nv_bfloat162*)&Cb[(size_t)(r0 + 8) * ldc + c0] = h1;
                }
            }
        }
    }
}

// Deterministic fixed-order reduction of XPK split-K partials -> fp32 + bf16.
__global__ void xdbl_reduce(const float* __restrict__ part,
                            float* __restrict__ outf,
                            __nv_bfloat16* __restrict__ outb, int n)
{
    int i = blockIdx.x * blockDim.x + threadIdx.x;
    if (i >= n) return;
    float s = part[i];
#pragma unroll
    for (int z = 1; z < XPK; z++) s += part[(size_t)z * n + i];
    outf[i] = s;
    outb[i] = __float2bfloat16(s);
}

// ---------------------------------------------------------------------------
__global__ void f2bf_all(const float* __restrict__ s1, const float* __restrict__ s2,
                         const float* __restrict__ s3, const float* __restrict__ s4,
                         __nv_bfloat16* __restrict__ d1, __nv_bfloat16* __restrict__ d2,
                         __nv_bfloat16* __restrict__ d3, __nv_bfloat16* __restrict__ d4,
                         int n1, int n2, int n3, int n4)
{
    int i = blockIdx.x * blockDim.x + threadIdx.x;
    if (i < n1) { d1[i] = __float2bfloat16(s1[i]); return; }
    i -= n1;
    if (i < n2) { d2[i] = __float2bfloat16(s2[i]); return; }
    i -= n2;
    if (i < n3) { d3[i] = __float2bfloat16(s3[i]); return; }
    i -= n3;
    if (i < n4) d4[i] = __float2bfloat16(s4[i]);
}
__global__ void copy_kernel(const float* __restrict__ src, float* __restrict__ dst,
                            __nv_bfloat16* __restrict__ dstb, int n)
{
    int i = blockIdx.x * blockDim.x + threadIdx.x;
    if (i < n) { float v = src[i]; dst[i] = v; dstb[i] = __float2bfloat16(v); }
}

// Causal depthwise conv (width 4) + bias + SiLU; fp32 + bf16 outputs.
__global__ void conv_silu_kernel(const float* __restrict__ xz,
                                 const float* __restrict__ cw,
                                 const float* __restrict__ cb,
                                 float* __restrict__ xi,
                                 __nv_bfloat16* __restrict__ xib)
{
    int idx = blockIdx.x * blockDim.x + threadIdx.x;
    if (idx >= NTOK * DI) return;
    int d = idx % DI;
    int n = idx / DI;
    int t = n % SEQ;
    float acc = cb[d];
#pragma unroll
    for (int k = 0; k < 4; k++) {
        int tt = t - 3 + k;
        if (tt >= 0)
            acc = fmaf(cw[d * 4 + k], xz[(size_t)(n - 3 + k) * (2 * DI) + d], acc);
    }
    float v = siluf(acc);
    xi[idx] = v;
    xib[idx] = __float2bfloat16(v);
}

// ---------------------------------------------------------------------------
// Chunked selective scan. scanA folds +u*D and writes ypart bf16.
// ---------------------------------------------------------------------------
__device__ __forceinline__ void scan_coeffs(
    const float* A_log, int d, int sub, float* Av, bool& trick)
{
#pragma unroll
    for (int i = 0; i < 4; i++)
        Av[i] = -__expf(A_log[d * DS + sub * 4 + i]);
    int e0 = sub * 4 + 1;
    trick = true;
#pragma unroll
    for (int i = 0; i < 4; i++)
        trick = trick && (fabsf(Av[i] + (float)(e0 + i)) < 3e-4f * (float)(e0 + i));
}
__device__ __forceinline__ void scan_dA(bool trick, const float* Av, int sub,
                                        float dlt, float* a)
{
    if (trick) {
        float r = fexp(-dlt);
        float r2 = r * r, r4 = r2 * r2;
        float p = r;
        if (sub & 1) p *= r4;
        if (sub & 2) p *= r4 * r4;
        a[0] = p; a[1] = p * r; a[2] = a[1] * r; a[3] = a[2] * r;
    } else {
        a[0] = fexp(dlt * Av[0]); a[1] = fexp(dlt * Av[1]);
        a[2] = fexp(dlt * Av[2]); a[3] = fexp(dlt * Av[3]);
    }
}

__global__ __launch_bounds__(128) void scanA(
    const float* __restrict__ xdbl, const float* __restrict__ delta,
    const float* __restrict__ xi, const float* __restrict__ A_log,
    const float* __restrict__ Dv,
    __nv_bfloat16* __restrict__ ypart, float* __restrict__ apv,
    float* __restrict__ hev)
{
    int gt  = blockIdx.x * 128 + threadIdx.x;
    int sub = gt & 3;
    int ch  = gt >> 2;                 // (b*DI+d)*NCH + c
    if (ch >= NB * DI * NCH) return;
    int c  = ch % NCH;
    int bd = ch / NCH;
    int d  = bd % DI, b = bd / DI;

    float Av[4]; bool trick;
    scan_coeffs(A_log, d, sub, Av, trick);
    float Dd = Dv[d];

    float h[4] = {0.f, 0.f, 0.f, 0.f};
    float ap[4] = {1.f, 1.f, 1.f, 1.f};
    const int base = b * SEQ + c * CL;

    for (int t = 0; t < CL; t++) {
        int n = base + t;
        float dlt = __ldg(&delta[(size_t)n * DI + d]);
        float u   = __ldg(&xi[(size_t)n * DI + d]);
        float4 Bv = __ldg((const float4*)(xdbl + (size_t)n * 96 + 64 + sub * 4));
        float4 Cv = __ldg((const float4*)(xdbl + (size_t)n * 96 + 80 + sub * 4));
        float a[4];
        scan_dA(trick, Av, sub, dlt, a);
        float du = dlt * u;
#pragma unroll
        for (int i = 0; i < 4; i++) ap[i] *= a[i];
        h[0] = fmaf(a[0], h[0], Bv.x * du);
        h[1] = fmaf(a[1], h[1], Bv.y * du);
        h[2] = fmaf(a[2], h[2], Bv.z * du);
        h[3] = fmaf(a[3], h[3], Bv.w * du);
        float yp = h[0] * Cv.x;
        yp = fmaf(h[1], Cv.y, yp);
        yp = fmaf(h[2], Cv.z, yp);
        yp = fmaf(h[3], Cv.w, yp);
        yp += __shfl_xor_sync(0xffffffffu, yp, 1);
        yp += __shfl_xor_sync(0xffffffffu, yp, 2);
        if (sub == 0)
            ypart[(size_t)n * DI + d] = __float2bfloat16(yp + u * Dd);
    }
#pragma unroll
    for (int i = 0; i < 4; i++) {
        apv[ch * 16 + sub * 4 + i] = ap[i];
        hev[ch * 16 + sub * 4 + i] = h[i];
    }
}

__global__ void scanB(const float* __restrict__ apv, const float* __restrict__ hev,
                      float* __restrict__ h0v)
{
    int i = blockIdx.x * 256 + threadIdx.x;   // over NB*DI*DS
    if (i >= NB * DI * DS) return;
    int s  = i & 15;
    int bd = i >> 4;
    float h = 0.0f;
#pragma unroll
    for (int c = 0; c < NCH; c++) {
        int idx = (bd * NCH + c) * 16 + s;
        h0v[idx] = h;
        h = fmaf(apv[idx], h, hev[idx]);
    }
}

__global__ __launch_bounds__(128) void scanC(
    const float* __restrict__ xdbl, const float* __restrict__ delta,
    const float* __restrict__ xz, const float* __restrict__ A_log,
    const __nv_bfloat16* __restrict__ ypart, const float* __restrict__ h0v,
    __nv_bfloat16* __restrict__ ybf)
{
    int gt  = blockIdx.x * 128 + threadIdx.x;
    int sub = gt & 3;
    int ch  = gt >> 2;
    if (ch >= NB * DI * NCH) return;
    int c  = ch % NCH;
    int bd = ch / NCH;
    int d  = bd % DI, b = bd / DI;

    float Av[4]; bool trick;
    scan_coeffs(A_log, d, sub, Av, trick);

    float h0[4], P[4] = {1.f, 1.f, 1.f, 1.f};
#pragma unroll
    for (int i = 0; i < 4; i++) h0[i] = h0v[ch * 16 + sub * 4 + i];

    const int base = b * SEQ + c * CL;
    for (int t = 0; t < CL; t++) {
        int n = base + t;
        float dlt = __ldg(&delta[(size_t)n * DI + d]);
        float4 Cv = __ldg((const float4*)(xdbl + (size_t)n * 96 + 80 + sub * 4));
        float a[4];
        scan_dA(trick, Av, sub, dlt, a);
#pragma unroll
        for (int i = 0; i < 4; i++) P[i] *= a[i];
        float corr = (P[0] * h0[0]) * Cv.x;
        corr = fmaf(P[1] * h0[1], Cv.y, corr);
        corr = fmaf(P[2] * h0[2], Cv.z, corr);
        corr = fmaf(P[3] * h0[3], Cv.w, corr);
        corr += __shfl_xor_sync(0xffffffffu, corr, 1);
        corr += __shfl_xor_sync(0xffffffffu, corr, 2);
        if (sub == 0) {
            float y = __bfloat162float(ypart[(size_t)n * DI + d]) + corr;
            float zv = __ldg(&xz[(size_t)n * (2 * DI) + DI + d]);
            ybf[(size_t)n * DI + d] = __float2bfloat16(y * siluf(zv));
        }
    }
}

// LayerNorm with fused residual: x = LN(tmp + x)*w + b; fp32 + bf16 outputs.
__global__ __launch_bounds__(256) void ln_kernel(
    const float* __restrict__ tmp, float* __restrict__ x,
    __nv_bfloat16* __restrict__ xb,
    const float* __restrict__ w, const float* __restrict__ bb)
{
    int n = blockIdx.x;
    int tid = threadIdx.x;
    __shared__ float sred[40];

    float v[4];
    float s = 0.0f;
#pragma unroll
    for (int i = 0; i < 4; i++) {
        int c = tid + 256 * i;
        v[i] = tmp[(size_t)n * DM + c] + x[(size_t)n * DM + c];
        s += v[i];
    }
    for (int o = 16; o; o >>= 1) s += __shfl_xor_sync(0xffffffffu, s, o);
    if ((tid & 31) == 0) sred[tid >> 5] = s;
    __syncthreads();
    if (tid < 8) {
        s = sred[tid];
        for (int o = 4; o; o >>= 1) s += __shfl_xor_sync(0xffu, s, o);
        if (tid == 0) sred[32] = s;
    }
    __syncthreads();
    float mu = sred[32] * (1.0f / DM);

    float s2 = 0.0f;
#pragma unroll
    for (int i = 0; i < 4; i++) {
        float dv = v[i] - mu;
        s2 += dv * dv;
    }
    for (int o = 16; o; o >>= 1) s2 += __shfl_xor_sync(0xffffffffu, s2, o);
    if ((tid & 31) == 0) sred[tid >> 5] = s2;
    __syncthreads();
    if (tid < 8) {
        s2 = sred[tid];
        for (int o = 4; o; o >>= 1) s2 += __shfl_xor_sync(0xffu, s2, o);
        if (tid == 0) sred[33] = s2;
    }
    __syncthreads();
    float inv = rsqrtf(sred[33] * (1.0f / DM) + 1e-5f);

#pragma unroll
    for (int i = 0; i < 4; i++) {
        int c = tid + 256 * i;
        float o = (v[i] - mu) * inv * w[c] + bb[c];
        x[(size_t)n * DM + c] = o;
        xb[(size_t)n * DM + c] = __float2bfloat16(o);
    }
}

// Layer-6 shortcut: out_proj restricted to last token of each batch.
__global__ __launch_bounds__(256) void final_out_kernel(
    const __nv_bfloat16* __restrict__ y, const __nv_bfloat16* __restrict__ outw,
    float* __restrict__ tmp4)
{
    int b = blockIdx.x, col = blockIdx.y * 256 + threadIdx.x;
    const __nv_bfloat16* yr = y + (size_t)(b * SEQ + SEQ - 1) * DI;
    const __nv_bfloat16* wr = outw + (size_t)col * DI;
    __shared__ __nv_bfloat16 ys[DI];
    for (int i = threadIdx.x; i < DI; i += 256) ys[i] = yr[i];
    __syncthreads();
    float s = 0.0f;
#pragma unroll 4
    for (int k = 0; k < DI; k += 8) {
        uint4 wv = *(const uint4*)(wr + k);
        const __nv_bfloat162* w2 = (const __nv_bfloat162*)&wv;
        const __nv_bfloat162* y2 = (const __nv_bfloat162*)&ys[k];
#pragma unroll
        for (int j = 0; j < 4; j++) {
            s = fmaf(__bfloat162float(y2[j].x), __bfloat162float(w2[j].x), s);
            s = fmaf(__bfloat162float(y2[j].y), __bfloat162float(w2[j].y), s);
        }
    }
    tmp4[b * DM + col] = s;
}

// Layer-6 LN + prediction fused, last tokens only.
__global__ __launch_bounds__(256) void final_ln_pred(
    const float* __restrict__ tmp4, const float* __restrict__ x,
    const float* __restrict__ w, const float* __restrict__ bb,
    const float* __restrict__ pw, const float* __restrict__ pb,
    float* __restrict__ out)
{
    int b = blockIdx.x;
    int tid = threadIdx.x;
    __shared__ float sred[40];
    const float* row = x + (size_t)(b * SEQ + SEQ - 1) * DM;

    float v[4];
    float s = 0.0f;
#pragma unroll
    for (int i = 0; i < 4; i++) {
        int c = tid + 256 * i;
        v[i] = tmp4[b * DM + c] + row[c];
        s += v[i];
    }
    for (int o = 16; o; o >>= 1) s += __shfl_xor_sync(0xffffffffu, s, o);
    if ((tid & 31) == 0) sred[tid >> 5] = s;
    __syncthreads();
    if (tid < 8) {
        s = sred[tid];
        for (int o = 4; o; o >>= 1) s += __shfl_xor_sync(0xffu, s, o);
        if (tid == 0) sred[32] = s;
    }
    __syncthreads();
    float mu = sred[32] * (1.0f / DM);

    float s2 = 0.0f;
#pragma unroll
    for (int i = 0; i < 4; i++) { float dv = v[i] - mu; s2 += dv * dv; }
    for (int o = 16; o; o >>= 1) s2 += __shfl_xor_sync(0xffffffffu, s2, o);
    if ((tid & 31) == 0) sred[tid >> 5] = s2;
    __syncthreads();
    if (tid < 8) {
        s2 = sred[tid];
        for (int o = 4; o; o >>= 1) s2 += __shfl_xor_sync(0xffu, s2, o);
        if (tid == 0) sred[33] = s2;
    }
    __syncthreads();
    float inv = rsqrtf(sred[33] * (1.0f / DM) + 1e-5f);

    float s3 = 0.0f;
#pragma unroll
    for (int i = 0; i < 4; i++) {
        int c = tid + 256 * i;
        float o = (v[i] - mu) * inv * w[c] + bb[c];
        s3 = fmaf(o, pw[c], s3);
    }
    for (int o = 16; o; o >>= 1) s3 += __shfl_xor_sync(0xffffffffu, s3, o);
    if ((tid & 31) == 0) sred[tid >> 5] = s3;
    __syncthreads();
    if (tid < 8) {
        s3 = sred[tid];
        for (int o = 4; o; o >>= 1) s3 += __shfl_xor_sync(0xffu, s3, o);
        if (tid == 0) out[b] = s3 + pb[0];
    }
}

// ---------------------------------------------------------------------------
extern "C" void kernel_launch(void* const* d_in, const int* in_sizes, int n_in,
                              void* d_out, int out_size)
{
    const float* x_in  = (const float*)d_in[0];
    const float* inw   = (const float*)d_in[1];
    const float* convw = (const float*)d_in[2];
    const float* convb = (const float*)d_in[3];
    const float* xpw   = (const float*)d_in[4];
    const float* dtw   = (const float*)d_in[5];
    const float* dtb   = (const float*)d_in[6];
    const float* Alog  = (const float*)d_in[7];
    const float* Dv    = (const float*)d_in[8];
    const float* outw  = (const float*)d_in[9];
    const float* lnw   = (const float*)d_in[10];
    const float* lnb   = (const float*)d_in[11];
    const float* predw = (const float*)d_in[12];
    const float* predb = (const float*)d_in[13];
    float* out = (float*)d_out;

    float *p_x, *p_xz, *p_xi, *p_xdbl, *p_xdp, *p_delta, *p_tmp, *p_tmp4;
    float *p_ap, *p_he, *p_h0;
    __nv_bfloat16 *p_ypbf, *p_xbf, *p_xibf, *p_ybf, *p_xdblbf;
    __nv_bfloat16 *p_inwb, *p_xpwb, *p_dtwb, *p_outwb;
    cudaGetSymbolAddress((void**)&p_x, g_x);
    cudaGetSymbolAddress((void**)&p_xz, g_xz);
    cudaGetSymbolAddress((void**)&p_xi, g_xi);
    cudaGetSymbolAddress((void**)&p_xdbl, g_xdbl);
    cudaGetSymbolAddress((void**)&p_xdp, g_xdp);
    cudaGetSymbolAddress((void**)&p_delta, g_delta);
    cudaGetSymbolAddress((void**)&p_tmp, g_tmp);
    cudaGetSymbolAddress((void**)&p_tmp4, g_tmp4);
    cudaGetSymbolAddress((void**)&p_ap, g_ap);
    cudaGetSymbolAddress((void**)&p_he, g_he);
    cudaGetSymbolAddress((void**)&p_h0, g_h0);
    cudaGetSymbolAddress((void**)&p_ypbf, g_ypbf);
    cudaGetSymbolAddress((void**)&p_xbf, g_xbf);
    cudaGetSymbolAddress((void**)&p_xibf, g_xibf);
    cudaGetSymbolAddress((void**)&p_ybf, g_ybf);
    cudaGetSymbolAddress((void**)&p_xdblbf, g_xdblbf);
    cudaGetSymbolAddress((void**)&p_inwb, g_inw_bf);
    cudaGetSymbolAddress((void**)&p_xpwb, g_xpw_bf);
    cudaGetSymbolAddress((void**)&p_dtwb, g_dtw_bf);
    cudaGetSymbolAddress((void**)&p_outwb, g_outw_bf);

    cudaFuncSetAttribute(bgemm<0,0>, cudaFuncAttributeMaxDynamicSharedMemorySize, GSMEM);
    cudaFuncSetAttribute(bgemm<1,0>, cudaFuncAttributeMaxDynamicSharedMemorySize, GSMEM);
    cudaFuncSetAttribute(bgemm<0,1>, cudaFuncAttributeMaxDynamicSharedMemorySize, GSMEM);

    // One launch for all weight conversions
    {
        int n1 = NL * 2 * DI * DM, n2 = NL * 96 * DI, n3 = NL * DI * DR, n4 = NL * DM * DI;
        int nt = n1 + n2 + n3 + n4;
        f2bf_all<<<(nt + 255) / 256, 256>>>(inw, xpw, dtw, outw,
                                            p_inwb, p_xpwb, p_dtwb, p_outwb,
                                            n1, n2, n3, n4);
    }
    copy_kernel<<<(NTOK * DM + 255) / 256, 256>>>(x_in, p_x, p_xbf, NTOK * DM);

    for (int l = 0; l < NL; l++) {
        // 1) xz = x @ in_proj_w^T
        bgemm<0,0><<<dim3((2 * DI) / 128, NTOK / 128), 256, GSMEM>>>(
            p_xbf, p_inwb + (size_t)l * 2 * DI * DM, p_xz, nullptr, nullptr,
            NTOK, 2 * DI, DM, DM, DM, 2 * DI);

        // 2) xi = silu(causal_conv(xz[:, :DI]))
        conv_silu_kernel<<<(NTOK * DI + 255) / 256, 256>>>(
            p_xz, convw + (size_t)l * DI * 4, convb + (size_t)l * DI, p_xi, p_xibf);

        // 3) x_dbl = xi @ x_proj_w^T  — split-K x4 + deterministic reduce
        bgemm<0,1><<<dim3(1, NTOK / 128, XPK), 256, GSMEM>>>(
            p_xibf, p_xpwb + (size_t)l * 96 * DI, p_xdp, nullptr, nullptr,
            NTOK, 96, DI / XPK, DI, DI, 96);
        xdbl_reduce<<<(NTOK * 96 + 255) / 256, 256>>>(
            p_xdp, p_xdbl, p_xdblbf, NTOK * 96);

        // 4) delta = softplus(x_dbl[:, :64] @ dt_w^T + dt_b)
        bgemm<1,0><<<dim3(DI / 128, NTOK / 128), 256, GSMEM>>>(
            p_xdblbf, p_dtwb + (size_t)l * DI * DR, p_delta, nullptr,
            dtb + (size_t)l * DI,
            NTOK, DI, DR, 96, DR, DI);

        // 5) chunked selective scan (scanA folds +u*D, writes ypart bf16)
        scanA<<<(NB * DI * NCH * 4) / 128, 128>>>(
            p_xdbl, p_delta, p_xi, Alog + (size_t)l * DI * DS,
            Dv + (size_t)l * DI, p_ypbf, p_ap, p_he);
        scanB<<<(NB * DI * DS + 255) / 256, 256>>>(p_ap, p_he, p_h0);
        scanC<<<(NB * DI * NCH * 4) / 128, 128>>>(
            p_xdbl, p_delta, p_xz, Alog + (size_t)l * DI * DS,
            p_ypbf, p_h0, p_ybf);

        if (l < NL - 1) {
            // 6) tmp = y @ out_proj_w^T
            bgemm<0,0><<<dim3(DM / 128, NTOK / 128), 256, GSMEM>>>(
                p_ybf, p_outwb + (size_t)l * DM * DI, p_tmp, nullptr, nullptr,
                NTOK, DM, DI, DI, DI, DM);

            // 7) x = LN(tmp + x)
            ln_kernel<<<NTOK, 256>>>(p_tmp, p_x, p_xbf,
                                     lnw + (size_t)l * DM, lnb + (size_t)l * DM);
        } else {
            final_out_kernel<<<dim3(NB, DM / 256), 256>>>(
                p_ybf, p_outwb + (size_t)l * DM * DI, p_tmp4);
            final_ln_pred<<<NB, 256>>>(
                p_tmp4, p_x, lnw + (size_t)l * DM, lnb + (size_t)l * DM,
                predw, predb, out);
        }
    }
}

// round 16
// speedup vs baseline: 1.1770x; 1.0165x over previous
#include <cuda_runtime.h>
#include <cuda_bf16.h>
#include <math.h>
#include <stdint.h>

#define NL 6
#define NB 4
#define SEQ 2048
#define DM 1024
#define DI 2048
#define DS 16
#define DR 64
#define NTOK (NB*SEQ)   // 8192
#define NCH 16          // scan chunks per sequence
#define CL (SEQ/NCH)    // 128 steps per chunk
#define XPK 4           // split-K factor for x_proj

// ---------------- scratch (device globals; no allocations allowed) ----------
__device__ float g_x[NTOK*DM];
__device__ float g_xdbl[NTOK*96];
__device__ float g_xdp[XPK*NTOK*96];
__device__ float g_delta[NTOK*DI];
__device__ float g_tmp[NTOK*DM];
__device__ float g_tmp4[NB*DM];
__device__ float g_ap[NB*DI*NCH*DS];
__device__ float g_he[NB*DI*NCH*DS];
__device__ float g_h0[NB*DI*NCH*DS];

__device__ __nv_bfloat16 g_xzbf[NTOK*2*DI];
__device__ __nv_bfloat16 g_ypbf[NTOK*DI];
__device__ __nv_bfloat16 g_xbf[NTOK*DM];
__device__ __nv_bfloat16 g_xibf[NTOK*DI];
__device__ __nv_bfloat16 g_ybf[NTOK*DI];
__device__ __nv_bfloat16 g_xdblbf[NTOK*96];
__device__ __nv_bfloat16 g_inw_bf[NL*2*DI*DM];
__device__ __nv_bfloat16 g_xpw_bf[NL*96*DI];
__device__ __nv_bfloat16 g_dtw_bf[NL*DI*DR];
__device__ __nv_bfloat16 g_outw_bf[NL*DM*DI];

// -------------------------- math helpers ------------------------------------
__device__ __forceinline__ float siluf(float x) { return x / (1.0f + __expf(-x)); }
__device__ __forceinline__ float fexp(float x) {
    float y = x * 1.4426950408889634f;
    float t = y + 12582912.0f;
    int   e = (__float_as_int(t) & 0x7FFFFF) - 0x400000;
    float f = y - (t - 12582912.0f);
    float p = 1.5403530e-4f;
    p = fmaf(p, f, 1.3333558e-3f);
    p = fmaf(p, f, 9.6181291e-3f);
    p = fmaf(p, f, 5.5504109e-2f);
    p = fmaf(p, f, 2.4022651e-1f);
    p = fmaf(p, f, 6.9314718e-1f);
    p = fmaf(p, f, 1.0f);
    if (e < -120) return 0.0f;
    return __int_as_float(__float_as_int(p) + (e << 23));
}
__device__ __forceinline__ float softp(float x) {
    return fmaxf(x, 0.0f) + log1pf(fexp(-fabsf(x)));
}
__device__ __forceinline__ uint32_t smem_u32(const void* p) {
    uint32_t a;
    asm("{ .reg .u64 t; cvta.to.shared.u64 t, %1; cvt.u32.u64 %0, t; }" : "=r"(a) : "l"(p));
    return a;
}
__device__ __forceinline__ void cp16(uint32_t dst, const void* src) {
    asm volatile("cp.async.cg.shared.global [%0], [%1], 16;" :: "r"(dst), "l"(src) : "memory");
}
__device__ __forceinline__ void mma_bf16(float* d, const uint32_t* a, const uint32_t* b) {
    asm volatile(
        "mma.sync.aligned.m16n8k16.row.col.f32.bf16.bf16.f32 "
        "{%0,%1,%2,%3}, {%4,%5,%6,%7}, {%8,%9}, {%0,%1,%2,%3};"
        : "+f"(d[0]), "+f"(d[1]), "+f"(d[2]), "+f"(d[3])
        : "r"(a[0]), "r"(a[1]), "r"(a[2]), "r"(a[3]), "r"(b[0]), "r"(b[1]));
}
__device__ __forceinline__ void ldsm4(uint32_t addr, uint32_t& r0, uint32_t& r1,
                                      uint32_t& r2, uint32_t& r3) {
    asm volatile("ldmatrix.sync.aligned.m8n8.x4.shared.b16 {%0,%1,%2,%3}, [%4];"
                 : "=r"(r0), "=r"(r1), "=r"(r2), "=r"(r3) : "r"(addr));
}

// ---------------------------------------------------------------------------
// bf16 mma.sync GEMM (winning R14/R15 config): 128x128 CTA tile, BK=32,
// 8 warps, 3-stage cp.async pipeline, one sync per K-iter, ldmatrix.x4.
// MODE 0: fp32 store.  MODE 1: softplus(acc+bias) fp32.  MODE 3: bf16-only.
// SPLITK 1: blockIdx.z selects K-slice of length K; partials at C + z*M*ldc.
// ---------------------------------------------------------------------------
#define GLDS 40
#define GASZ (128 * GLDS * 2)
#define GSTG (2 * GASZ)
#define GSMEM (3 * GSTG)

template<int MODE, int SPLITK>
__global__ __launch_bounds__(256, 2) void bgemm(
    const __nv_bfloat16* __restrict__ A, const __nv_bfloat16* __restrict__ Bw,
    float* __restrict__ C, __nv_bfloat16* __restrict__ Cb,
    const float* __restrict__ bias,
    int M, int N, int K, int lda, int ldb, int ldc)
{
    constexpr int BK = 32;
    constexpr int MT = 2, NT = 8;

    extern __shared__ __nv_bfloat16 dsmem[];
    const uint32_t sbase = smem_u32(dsmem);

    if (SPLITK) {
        size_t ko = (size_t)blockIdx.z * K;
        A += ko; Bw += ko;
        C += (size_t)blockIdx.z * M * ldc;
    }

    const int tid = threadIdx.x, lane = tid & 31, warp = tid >> 5;
    const int m0 = blockIdx.y * 128, n0 = blockIdx.x * 128;
    const int wm = (warp >> 1) * 32, wn = (warp & 1) * 64;
    const int grp = lane >> 2, thr = lane & 3;

    const int a_row = wm + (lane & 15);
    const int a_col = (lane >> 4) * 8;
    const int b_row = wn + (lane & 7) + ((lane >> 4) << 3);
    const int b_col = ((lane >> 3) & 1) * 8;

    float acc[MT][NT][4];
#pragma unroll
    for (int i = 0; i < MT; i++)
#pragma unroll
        for (int j = 0; j < NT; j++)
#pragma unroll
            for (int q = 0; q < 4; q++) acc[i][j][q] = 0.0f;

    auto stage = [&](int kt, int s) {
        int k0 = kt << 5;
        uint32_t ab = sbase + s * GSTG;
        uint32_t bb = ab + GASZ;
#pragma unroll
        for (int i = 0; i < 2; i++) {
            int idx = tid + (i << 8);
            int r = idx >> 2, c = idx & 3;
            cp16(ab + (uint32_t)(r * (GLDS * 2) + c * 16),
                 A + (size_t)(m0 + r) * lda + k0 + c * 8);
        }
#pragma unroll
        for (int i = 0; i < 2; i++) {
            int idx = tid + (i << 8);
            int r = idx >> 2, c = idx & 3;
            int gr = n0 + r; if (gr >= N) gr = N - 1;
            cp16(bb + (uint32_t)(r * (GLDS * 2) + c * 16),
                 Bw + (size_t)gr * ldb + k0 + c * 8);
        }
        asm volatile("cp.async.commit_group;" ::: "memory");
    };

    auto comp = [&](int s) {
        uint32_t ab = sbase + s * GSTG;
        uint32_t bb = ab + GASZ;
#pragma unroll
        for (int kk = 0; kk < BK; kk += 16) {
            uint32_t af[MT][4], bf[NT][2];
#pragma unroll
            for (int mt = 0; mt < MT; mt++)
                ldsm4(ab + (uint32_t)(((a_row + mt * 16) * GLDS + kk + a_col) * 2),
                      af[mt][0], af[mt][1], af[mt][2], af[mt][3]);
#pragma unroll
            for (int np = 0; np < NT / 2; np++)
                ldsm4(bb + (uint32_t)(((b_row + np * 16) * GLDS + kk + b_col) * 2),
                      bf[2 * np][0], bf[2 * np][1], bf[2 * np + 1][0], bf[2 * np + 1][1]);
#pragma unroll
            for (int mt = 0; mt < MT; mt++)
#pragma unroll
                for (int nt = 0; nt < NT; nt++)
                    mma_bf16(acc[mt][nt], af[mt], bf[nt]);
        }
    };

    const int NC = K >> 5;
    stage(0, 0);
    stage(1, 1);
    for (int kt = 0; kt < NC; kt++) {
        if (kt + 1 < NC)
            asm volatile("cp.async.wait_group 1;" ::: "memory");
        else
            asm volatile("cp.async.wait_group 0;" ::: "memory");
        __syncthreads();
        comp(kt % 3);
        if (kt + 2 < NC) stage(kt + 2, (kt + 2) % 3);
    }

#pragma unroll
    for (int mt = 0; mt < MT; mt++) {
        int r0 = m0 + wm + mt * 16 + grp;
#pragma unroll
        for (int nt = 0; nt < NT; nt++) {
            int c0 = n0 + wn + nt * 8 + thr * 2;
            if (c0 < N) {
                float v0 = acc[mt][nt][0], v1 = acc[mt][nt][1];
                float v2 = acc[mt][nt][2], v3 = acc[mt][nt][3];
                if (MODE == 1) {
                    float b0 = bias[c0], b1 = bias[c0 + 1];
                    v0 = softp(v0 + b0); v1 = softp(v1 + b1);
                    v2 = softp(v2 + b0); v3 = softp(v3 + b1);
                }
                if (MODE == 3) {
                    __nv_bfloat162 h0, h1;
                    h0.x = __float2bfloat16(v0); h0.y = __float2bfloat16(v1);
                    h1.x = __float2bfloat16(v2); h1.y = __float2bfloat16(v3);
                    *(__nv_bfloat162*)&Cb[(size_t)r0 * ldc + c0]       = h0;
                    *(__nv_bfloat162*)&Cb[(size_t)(r0 + 8) * ldc + c0] = h1;
                } else {
                    *(float2*)&C[(size_t)r0 * ldc + c0]       = make_float2(v0, v1);
                    *(float2*)&C[(size_t)(r0 + 8) * ldc + c0] = make_float2(v2, v3);
                }
            }
        }
    }
}

// Deterministic fixed-order reduction of XPK split-K partials -> fp32 + bf16.
__global__ void xdbl_reduce(const float* __restrict__ part,
                            float* __restrict__ outf,
                            __nv_bfloat16* __restrict__ outb, int n)
{
    int i = blockIdx.x * blockDim.x + threadIdx.x;
    if (i >= n) return;
    float s = part[i];
#pragma unroll
    for (int z = 1; z < XPK; z++) s += part[(size_t)z * n + i];
    outf[i] = s;
    outb[i] = __float2bfloat16(s);
}

// ---------------------------------------------------------------------------
__global__ void f2bf_all(const float* __restrict__ s1, const float* __restrict__ s2,
                         const float* __restrict__ s3, const float* __restrict__ s4,
                         __nv_bfloat16* __restrict__ d1, __nv_bfloat16* __restrict__ d2,
                         __nv_bfloat16* __restrict__ d3, __nv_bfloat16* __restrict__ d4,
                         int n1, int n2, int n3, int n4)
{
    int i = blockIdx.x * blockDim.x + threadIdx.x;
    if (i < n1) { d1[i] = __float2bfloat16(s1[i]); return; }
    i -= n1;
    if (i < n2) { d2[i] = __float2bfloat16(s2[i]); return; }
    i -= n2;
    if (i < n3) { d3[i] = __float2bfloat16(s3[i]); return; }
    i -= n3;
    if (i < n4) d4[i] = __float2bfloat16(s4[i]);
}
__global__ void copy_kernel(const float* __restrict__ src, float* __restrict__ dst,
                            __nv_bfloat16* __restrict__ dstb, int n)
{
    int i = blockIdx.x * blockDim.x + threadIdx.x;
    if (i < n) { float v = src[i]; dst[i] = v; dstb[i] = __float2bfloat16(v); }
}

// Causal depthwise conv (width 4) + bias + SiLU; bf16 in (xz), bf16 out.
__global__ void conv_silu_kernel(const __nv_bfloat16* __restrict__ xz,
                                 const float* __restrict__ cw,
                                 const float* __restrict__ cb,
                                 __nv_bfloat16* __restrict__ xib)
{
    int idx = blockIdx.x * blockDim.x + threadIdx.x;
    if (idx >= NTOK * DI) return;
    int d = idx % DI;
    int n = idx / DI;
    int t = n % SEQ;
    float acc = cb[d];
#pragma unroll
    for (int k = 0; k < 4; k++) {
        int tt = t - 3 + k;
        if (tt >= 0)
            acc = fmaf(cw[d * 4 + k],
                       __bfloat162float(xz[(size_t)(n - 3 + k) * (2 * DI) + d]), acc);
    }
    xib[idx] = __float2bfloat16(siluf(acc));
}

// ---------------------------------------------------------------------------
// Chunked selective scan. scanA folds +u*D (u from bf16), writes ypart bf16.
// ---------------------------------------------------------------------------
__device__ __forceinline__ void scan_coeffs(
    const float* A_log, int d, int sub, float* Av, bool& trick)
{
#pragma unroll
    for (int i = 0; i < 4; i++)
        Av[i] = -__expf(A_log[d * DS + sub * 4 + i]);
    int e0 = sub * 4 + 1;
    trick = true;
#pragma unroll
    for (int i = 0; i < 4; i++)
        trick = trick && (fabsf(Av[i] + (float)(e0 + i)) < 3e-4f * (float)(e0 + i));
}
__device__ __forceinline__ void scan_dA(bool trick, const float* Av, int sub,
                                        float dlt, float* a)
{
    if (trick) {
        float r = fexp(-dlt);
        float r2 = r * r, r4 = r2 * r2;
        float p = r;
        if (sub & 1) p *= r4;
        if (sub & 2) p *= r4 * r4;
        a[0] = p; a[1] = p * r; a[2] = a[1] * r; a[3] = a[2] * r;
    } else {
        a[0] = fexp(dlt * Av[0]); a[1] = fexp(dlt * Av[1]);
        a[2] = fexp(dlt * Av[2]); a[3] = fexp(dlt * Av[3]);
    }
}

__global__ __launch_bounds__(128) void scanA(
    const float* __restrict__ xdbl, const float* __restrict__ delta,
    const __nv_bfloat16* __restrict__ xi, const float* __restrict__ A_log,
    const float* __restrict__ Dv,
    __nv_bfloat16* __restrict__ ypart, float* __restrict__ apv,
    float* __restrict__ hev)
{
    int gt  = blockIdx.x * 128 + threadIdx.x;
    int sub = gt & 3;
    int ch  = gt >> 2;                 // (b*DI+d)*NCH + c
    if (ch >= NB * DI * NCH) return;
    int c  = ch % NCH;
    int bd = ch / NCH;
    int d  = bd % DI, b = bd / DI;

    float Av[4]; bool trick;
    scan_coeffs(A_log, d, sub, Av, trick);
    float Dd = Dv[d];

    float h[4] = {0.f, 0.f, 0.f, 0.f};
    float ap[4] = {1.f, 1.f, 1.f, 1.f};
    const int base = b * SEQ + c * CL;

    for (int t = 0; t < CL; t++) {
        int n = base + t;
        float dlt = __ldg(&delta[(size_t)n * DI + d]);
        float u   = __bfloat162float(__ldg(&xi[(size_t)n * DI + d]));
        float4 Bv = __ldg((const float4*)(xdbl + (size_t)n * 96 + 64 + sub * 4));
        float4 Cv = __ldg((const float4*)(xdbl + (size_t)n * 96 + 80 + sub * 4));
        float a[4];
        scan_dA(trick, Av, sub, dlt, a);
        float du = dlt * u;
#pragma unroll
        for (int i = 0; i < 4; i++) ap[i] *= a[i];
        h[0] = fmaf(a[0], h[0], Bv.x * du);
        h[1] = fmaf(a[1], h[1], Bv.y * du);
        h[2] = fmaf(a[2], h[2], Bv.z * du);
        h[3] = fmaf(a[3], h[3], Bv.w * du);
        float yp = h[0] * Cv.x;
        yp = fmaf(h[1], Cv.y, yp);
        yp = fmaf(h[2], Cv.z, yp);
        yp = fmaf(h[3], Cv.w, yp);
        yp += __shfl_xor_sync(0xffffffffu, yp, 1);
        yp += __shfl_xor_sync(0xffffffffu, yp, 2);
        if (sub == 0)
            ypart[(size_t)n * DI + d] = __float2bfloat16(yp + u * Dd);
    }
#pragma unroll
    for (int i = 0; i < 4; i++) {
        apv[ch * 16 + sub * 4 + i] = ap[i];
        hev[ch * 16 + sub * 4 + i] = h[i];
    }
}

__global__ void scanB(const float* __restrict__ apv, const float* __restrict__ hev,
                      float* __restrict__ h0v)
{
    int i = blockIdx.x * 256 + threadIdx.x;   // over NB*DI*DS
    if (i >= NB * DI * DS) return;
    int s  = i & 15;
    int bd = i >> 4;
    float h = 0.0f;
#pragma unroll
    for (int c = 0; c < NCH; c++) {
        int idx = (bd * NCH + c) * 16 + s;
        h0v[idx] = h;
        h = fmaf(apv[idx], h, hev[idx]);
    }
}

__global__ __launch_bounds__(128) void scanC(
    const float* __restrict__ xdbl, const float* __restrict__ delta,
    const __nv_bfloat16* __restrict__ xz, const float* __restrict__ A_log,
    const __nv_bfloat16* __restrict__ ypart, const float* __restrict__ h0v,
    __nv_bfloat16* __restrict__ ybf)
{
    int gt  = blockIdx.x * 128 + threadIdx.x;
    int sub = gt & 3;
    int ch  = gt >> 2;
    if (ch >= NB * DI * NCH) return;
    int c  = ch % NCH;
    int bd = ch / NCH;
    int d  = bd % DI, b = bd / DI;

    float Av[4]; bool trick;
    scan_coeffs(A_log, d, sub, Av, trick);

    float h0[4], P[4] = {1.f, 1.f, 1.f, 1.f};
#pragma unroll
    for (int i = 0; i < 4; i++) h0[i] = h0v[ch * 16 + sub * 4 + i];

    const int base = b * SEQ + c * CL;
    for (int t = 0; t < CL; t++) {
        int n = base + t;
        float dlt = __ldg(&delta[(size_t)n * DI + d]);
        float4 Cv = __ldg((const float4*)(xdbl + (size_t)n * 96 + 80 + sub * 4));
        float a[4];
        scan_dA(trick, Av, sub, dlt, a);
#pragma unroll
        for (int i = 0; i < 4; i++) P[i] *= a[i];
        float corr = (P[0] * h0[0]) * Cv.x;
        corr = fmaf(P[1] * h0[1], Cv.y, corr);
        corr = fmaf(P[2] * h0[2], Cv.z, corr);
        corr = fmaf(P[3] * h0[3], Cv.w, corr);
        corr += __shfl_xor_sync(0xffffffffu, corr, 1);
        corr += __shfl_xor_sync(0xffffffffu, corr, 2);
        if (sub == 0) {
            float y = __bfloat162float(ypart[(size_t)n * DI + d]) + corr;
            float zv = __bfloat162float(__ldg(&xz[(size_t)n * (2 * DI) + DI + d]));
            ybf[(size_t)n * DI + d] = __float2bfloat16(y * siluf(zv));
        }
    }
}

// LayerNorm with fused residual: x = LN(tmp + x)*w + b; fp32 + bf16 outputs.
__global__ __launch_bounds__(256) void ln_kernel(
    const float* __restrict__ tmp, float* __restrict__ x,
    __nv_bfloat16* __restrict__ xb,
    const float* __restrict__ w, const float* __restrict__ bb)
{
    int n = blockIdx.x;
    int tid = threadIdx.x;
    __shared__ float sred[40];

    float v[4];
    float s = 0.0f;
#pragma unroll
    for (int i = 0; i < 4; i++) {
        int c = tid + 256 * i;
        v[i] = tmp[(size_t)n * DM + c] + x[(size_t)n * DM + c];
        s += v[i];
    }
    for (int o = 16; o; o >>= 1) s += __shfl_xor_sync(0xffffffffu, s, o);
    if ((tid & 31) == 0) sred[tid >> 5] = s;
    __syncthreads();
    if (tid < 8) {
        s = sred[tid];
        for (int o = 4; o; o >>= 1) s += __shfl_xor_sync(0xffu, s, o);
        if (tid == 0) sred[32] = s;
    }
    __syncthreads();
    float mu = sred[32] * (1.0f / DM);

    float s2 = 0.0f;
#pragma unroll
    for (int i = 0; i < 4; i++) {
        float dv = v[i] - mu;
        s2 += dv * dv;
    }
    for (int o = 16; o; o >>= 1) s2 += __shfl_xor_sync(0xffffffffu, s2, o);
    if ((tid & 31) == 0) sred[tid >> 5] = s2;
    __syncthreads();
    if (tid < 8) {
        s2 = sred[tid];
        for (int o = 4; o; o >>= 1) s2 += __shfl_xor_sync(0xffu, s2, o);
        if (tid == 0) sred[33] = s2;
    }
    __syncthreads();
    float inv = rsqrtf(sred[33] * (1.0f / DM) + 1e-5f);

#pragma unroll
    for (int i = 0; i < 4; i++) {
        int c = tid + 256 * i;
        float o = (v[i] - mu) * inv * w[c] + bb[c];
        x[(size_t)n * DM + c] = o;
        xb[(size_t)n * DM + c] = __float2bfloat16(o);
    }
}

// Layer-6 shortcut: out_proj restricted to last token of each batch.
__global__ __launch_bounds__(256) void final_out_kernel(
    const __nv_bfloat16* __restrict__ y, const __nv_bfloat16* __restrict__ outw,
    float* __restrict__ tmp4)
{
    int b = blockIdx.x, col = blockIdx.y * 256 + threadIdx.x;
    const __nv_bfloat16* yr = y + (size_t)(b * SEQ + SEQ - 1) * DI;
    const __nv_bfloat16* wr = outw + (size_t)col * DI;
    __shared__ __nv_bfloat16 ys[DI];
    for (int i = threadIdx.x; i < DI; i += 256) ys[i] = yr[i];
    __syncthreads();
    float s = 0.0f;
#pragma unroll 4
    for (int k = 0; k < DI; k += 8) {
        uint4 wv = *(const uint4*)(wr + k);
        const __nv_bfloat162* w2 = (const __nv_bfloat162*)&wv;
        const __nv_bfloat162* y2 = (const __nv_bfloat162*)&ys[k];
#pragma unroll
        for (int j = 0; j < 4; j++) {
            s = fmaf(__bfloat162float(y2[j].x), __bfloat162float(w2[j].x), s);
            s = fmaf(__bfloat162float(y2[j].y), __bfloat162float(w2[j].y), s);
        }
    }
    tmp4[b * DM + col] = s;
}

// Layer-6 LN + prediction fused, last tokens only.
__global__ __launch_bounds__(256) void final_ln_pred(
    const float* __restrict__ tmp4, const float* __restrict__ x,
    const float* __restrict__ w, const float* __restrict__ bb,
    const float* __restrict__ pw, const float* __restrict__ pb,
    float* __restrict__ out)
{
    int b = blockIdx.x;
    int tid = threadIdx.x;
    __shared__ float sred[40];
    const float* row = x + (size_t)(b * SEQ + SEQ - 1) * DM;

    float v[4];
    float s = 0.0f;
#pragma unroll
    for (int i = 0; i < 4; i++) {
        int c = tid + 256 * i;
        v[i] = tmp4[b * DM + c] + row[c];
        s += v[i];
    }
    for (int o = 16; o; o >>= 1) s += __shfl_xor_sync(0xffffffffu, s, o);
    if ((tid & 31) == 0) sred[tid >> 5] = s;
    __syncthreads();
    if (tid < 8) {
        s = sred[tid];
        for (int o = 4; o; o >>= 1) s += __shfl_xor_sync(0xffu, s, o);
        if (tid == 0) sred[32] = s;
    }
    __syncthreads();
    float mu = sred[32] * (1.0f / DM);

    float s2 = 0.0f;
#pragma unroll
    for (int i = 0; i < 4; i++) { float dv = v[i] - mu; s2 += dv * dv; }
    for (int o = 16; o; o >>= 1) s2 += __shfl_xor_sync(0xffffffffu, s2, o);
    if ((tid & 31) == 0) sred[tid >> 5] = s2;
    __syncthreads();
    if (tid < 8) {
        s2 = sred[tid];
        for (int o = 4; o; o >>= 1) s2 += __shfl_xor_sync(0xffu, s2, o);
        if (tid == 0) sred[33] = s2;
    }
    __syncthreads();
    float inv = rsqrtf(sred[33] * (1.0f / DM) + 1e-5f);

    float s3 = 0.0f;
#pragma unroll
    for (int i = 0; i < 4; i++) {
        int c = tid + 256 * i;
        float o = (v[i] - mu) * inv * w[c] + bb[c];
        s3 = fmaf(o, pw[c], s3);
    }
    for (int o = 16; o; o >>= 1) s3 += __shfl_xor_sync(0xffffffffu, s3, o);
    if ((tid & 31) == 0) sred[tid >> 5] = s3;
    __syncthreads();
    if (tid < 8) {
        s3 = sred[tid];
        for (int o = 4; o; o >>= 1) s3 += __shfl_xor_sync(0xffu, s3, o);
        if (tid == 0) out[b] = s3 + pb[0];
    }
}

// ---------------------------------------------------------------------------
extern "C" void kernel_launch(void* const* d_in, const int* in_sizes, int n_in,
                              void* d_out, int out_size)
{
    const float* x_in  = (const float*)d_in[0];
    const float* inw   = (const float*)d_in[1];
    const float* convw = (const float*)d_in[2];
    const float* convb = (const float*)d_in[3];
    const float* xpw   = (const float*)d_in[4];
    const float* dtw   = (const float*)d_in[5];
    const float* dtb   = (const float*)d_in[6];
    const float* Alog  = (const float*)d_in[7];
    const float* Dv    = (const float*)d_in[8];
    const float* outw  = (const float*)d_in[9];
    const float* lnw   = (const float*)d_in[10];
    const float* lnb   = (const float*)d_in[11];
    const float* predw = (const float*)d_in[12];
    const float* predb = (const float*)d_in[13];
    float* out = (float*)d_out;

    float *p_x, *p_xdbl, *p_xdp, *p_delta, *p_tmp, *p_tmp4;
    float *p_ap, *p_he, *p_h0;
    __nv_bfloat16 *p_xzbf, *p_ypbf, *p_xbf, *p_xibf, *p_ybf, *p_xdblbf;
    __nv_bfloat16 *p_inwb, *p_xpwb, *p_dtwb, *p_outwb;
    cudaGetSymbolAddress((void**)&p_x, g_x);
    cudaGetSymbolAddress((void**)&p_xdbl, g_xdbl);
    cudaGetSymbolAddress((void**)&p_xdp, g_xdp);
    cudaGetSymbolAddress((void**)&p_delta, g_delta);
    cudaGetSymbolAddress((void**)&p_tmp, g_tmp);
    cudaGetSymbolAddress((void**)&p_tmp4, g_tmp4);
    cudaGetSymbolAddress((void**)&p_ap, g_ap);
    cudaGetSymbolAddress((void**)&p_he, g_he);
    cudaGetSymbolAddress((void**)&p_h0, g_h0);
    cudaGetSymbolAddress((void**)&p_xzbf, g_xzbf);
    cudaGetSymbolAddress((void**)&p_ypbf, g_ypbf);
    cudaGetSymbolAddress((void**)&p_xbf, g_xbf);
    cudaGetSymbolAddress((void**)&p_xibf, g_xibf);
    cudaGetSymbolAddress((void**)&p_ybf, g_ybf);
    cudaGetSymbolAddress((void**)&p_xdblbf, g_xdblbf);
    cudaGetSymbolAddress((void**)&p_inwb, g_inw_bf);
    cudaGetSymbolAddress((void**)&p_xpwb, g_xpw_bf);
    cudaGetSymbolAddress((void**)&p_dtwb, g_dtw_bf);
    cudaGetSymbolAddress((void**)&p_outwb, g_outw_bf);

    cudaFuncSetAttribute(bgemm<0,0>, cudaFuncAttributeMaxDynamicSharedMemorySize, GSMEM);
    cudaFuncSetAttribute(bgemm<1,0>, cudaFuncAttributeMaxDynamicSharedMemorySize, GSMEM);
    cudaFuncSetAttribute(bgemm<3,0>, cudaFuncAttributeMaxDynamicSharedMemorySize, GSMEM);
    cudaFuncSetAttribute(bgemm<0,1>, cudaFuncAttributeMaxDynamicSharedMemorySize, GSMEM);

    // One launch for all weight conversions
    {
        int n1 = NL * 2 * DI * DM, n2 = NL * 96 * DI, n3 = NL * DI * DR, n4 = NL * DM * DI;
        int nt = n1 + n2 + n3 + n4;
        f2bf_all<<<(nt + 255) / 256, 256>>>(inw, xpw, dtw, outw,
                                            p_inwb, p_xpwb, p_dtwb, p_outwb,
                                            n1, n2, n3, n4);
    }
    copy_kernel<<<(NTOK * DM + 255) / 256, 256>>>(x_in, p_x, p_xbf, NTOK * DM);

    for (int l = 0; l < NL; l++) {
        // 1) xz = x @ in_proj_w^T  (bf16-only output)
        bgemm<3,0><<<dim3((2 * DI) / 128, NTOK / 128), 256, GSMEM>>>(
            p_xbf, p_inwb + (size_t)l * 2 * DI * DM, nullptr, p_xzbf, nullptr,
            NTOK, 2 * DI, DM, DM, DM, 2 * DI);

        // 2) xi = silu(causal_conv(xz[:, :DI]))  (bf16 in/out)
        conv_silu_kernel<<<(NTOK * DI + 255) / 256, 256>>>(
            p_xzbf, convw + (size_t)l * DI * 4, convb + (size_t)l * DI, p_xibf);

        // 3) x_dbl = xi @ x_proj_w^T  — split-K x4 + deterministic reduce
        bgemm<0,1><<<dim3(1, NTOK / 128, XPK), 256, GSMEM>>>(
            p_xibf, p_xpwb + (size_t)l * 96 * DI, p_xdp, nullptr, nullptr,
            NTOK, 96, DI / XPK, DI, DI, 96);
        xdbl_reduce<<<(NTOK * 96 + 255) / 256, 256>>>(
            p_xdp, p_xdbl, p_xdblbf, NTOK * 96);

        // 4) delta = softplus(x_dbl[:, :64] @ dt_w^T + dt_b)  (fp32, precision)
        bgemm<1,0><<<dim3(DI / 128, NTOK / 128), 256, GSMEM>>>(
            p_xdblbf, p_dtwb + (size_t)l * DI * DR, p_delta, nullptr,
            dtb + (size_t)l * DI,
            NTOK, DI, DR, 96, DR, DI);

        // 5) chunked selective scan
        scanA<<<(NB * DI * NCH * 4) / 128, 128>>>(
            p_xdbl, p_delta, p_xibf, Alog + (size_t)l * DI * DS,
            Dv + (size_t)l * DI, p_ypbf, p_ap, p_he);
        scanB<<<(NB * DI * DS + 255) / 256, 256>>>(p_ap, p_he, p_h0);
        scanC<<<(NB * DI * NCH * 4) / 128, 128>>>(
            p_xdbl, p_delta, p_xzbf, Alog + (size_t)l * DI * DS,
            p_ypbf, p_h0, p_ybf);

        if (l < NL - 1) {
            // 6) tmp = y @ out_proj_w^T  (fp32 for LN residual)
            bgemm<0,0><<<dim3(DM / 128, NTOK / 128), 256, GSMEM>>>(
                p_ybf, p_outwb + (size_t)l * DM * DI, p_tmp, nullptr, nullptr,
                NTOK, DM, DI, DI, DI, DM);

            // 7) x = LN(tmp + x)
            ln_kernel<<<NTOK, 256>>>(p_tmp, p_x, p_xbf,
                                     lnw + (size_t)l * DM, lnb + (size_t)l * DM);
        } else {
            final_out_kernel<<<dim3(NB, DM / 256), 256>>>(
                p_ybf, p_outwb + (size_t)l * DM * DI, p_tmp4);
            final_ln_pred<<<NB, 256>>>(
                p_tmp4, p_x, lnw + (size_t)l * DM, lnb + (size_t)l * DM,
                predw, predb, out);
        }
    }
}

// round 17
// speedup vs baseline: 1.2028x; 1.0219x over previous
#include <cuda_runtime.h>
#include <cuda_bf16.h>
#include <math.h>
#include <stdint.h>

#define NL 6
#define NB 4
#define SEQ 2048
#define DM 1024
#define DI 2048
#define DS 16
#define DR 64
#define NTOK (NB*SEQ)   // 8192
#define NCH 16          // scan chunks per sequence
#define CL (SEQ/NCH)    // 128 steps per chunk
#define XPK 4           // split-K factor for x_proj

// ---------------- scratch (device globals; no allocations allowed) ----------
__device__ float g_x[NTOK*DM];
__device__ float g_xdbl[NTOK*96];
__device__ float g_xdp[XPK*NTOK*96];
__device__ float g_tmp[NTOK*DM];
__device__ float g_tmp4[NB*DM];
__device__ float g_ap[NB*DI*NCH*DS];
__device__ float g_he[NB*DI*NCH*DS];
__device__ float g_h0[NB*DI*NCH*DS];

__device__ __nv_bfloat16 g_deltabf[NTOK*DI];
__device__ __nv_bfloat16 g_xzbf[NTOK*2*DI];
__device__ __nv_bfloat16 g_ypbf[NTOK*DI];
__device__ __nv_bfloat16 g_xbf[NTOK*DM];
__device__ __nv_bfloat16 g_xibf[NTOK*DI];
__device__ __nv_bfloat16 g_ybf[NTOK*DI];
__device__ __nv_bfloat16 g_xdblbf[NTOK*96];
__device__ __nv_bfloat16 g_inw_bf[NL*2*DI*DM];
__device__ __nv_bfloat16 g_xpw_bf[NL*96*DI];
__device__ __nv_bfloat16 g_dtw_bf[NL*DI*DR];
__device__ __nv_bfloat16 g_outw_bf[NL*DM*DI];

// -------------------------- math helpers ------------------------------------
__device__ __forceinline__ float siluf(float x) { return x / (1.0f + __expf(-x)); }
__device__ __forceinline__ float fexp(float x) {
    float y = x * 1.4426950408889634f;
    float t = y + 12582912.0f;
    int   e = (__float_as_int(t) & 0x7FFFFF) - 0x400000;
    float f = y - (t - 12582912.0f);
    float p = 1.5403530e-4f;
    p = fmaf(p, f, 1.3333558e-3f);
    p = fmaf(p, f, 9.6181291e-3f);
    p = fmaf(p, f, 5.5504109e-2f);
    p = fmaf(p, f, 2.4022651e-1f);
    p = fmaf(p, f, 6.9314718e-1f);
    p = fmaf(p, f, 1.0f);
    if (e < -120) return 0.0f;
    return __int_as_float(__float_as_int(p) + (e << 23));
}
__device__ __forceinline__ float softp(float x) {
    return fmaxf(x, 0.0f) + log1pf(fexp(-fabsf(x)));
}
__device__ __forceinline__ uint32_t smem_u32(const void* p) {
    uint32_t a;
    asm("{ .reg .u64 t; cvta.to.shared.u64 t, %1; cvt.u32.u64 %0, t; }" : "=r"(a) : "l"(p));
    return a;
}
__device__ __forceinline__ void cp16(uint32_t dst, const void* src) {
    asm volatile("cp.async.cg.shared.global [%0], [%1], 16;" :: "r"(dst), "l"(src) : "memory");
}
__device__ __forceinline__ void mma_bf16(float* d, const uint32_t* a, const uint32_t* b) {
    asm volatile(
        "mma.sync.aligned.m16n8k16.row.col.f32.bf16.bf16.f32 "
        "{%0,%1,%2,%3}, {%4,%5,%6,%7}, {%8,%9}, {%0,%1,%2,%3};"
        : "+f"(d[0]), "+f"(d[1]), "+f"(d[2]), "+f"(d[3])
        : "r"(a[0]), "r"(a[1]), "r"(a[2]), "r"(a[3]), "r"(b[0]), "r"(b[1]));
}
__device__ __forceinline__ void ldsm4(uint32_t addr, uint32_t& r0, uint32_t& r1,
                                      uint32_t& r2, uint32_t& r3) {
    asm volatile("ldmatrix.sync.aligned.m8n8.x4.shared.b16 {%0,%1,%2,%3}, [%4];"
                 : "=r"(r0), "=r"(r1), "=r"(r2), "=r"(r3) : "r"(addr));
}

// ---------------------------------------------------------------------------
// bf16 mma.sync GEMM (winning R14/R15 config): 128x128 CTA tile, BK=32,
// 8 warps, 3-stage cp.async pipeline, one sync per K-iter, ldmatrix.x4.
// MODE 0: fp32.  MODE 1: softplus(acc+bias) -> bf16.  MODE 3: bf16-only.
// SPLITK 1: blockIdx.z selects K-slice of length K; partials at C + z*M*ldc.
// ---------------------------------------------------------------------------
#define GLDS 40
#define GASZ (128 * GLDS * 2)
#define GSTG (2 * GASZ)
#define GSMEM (3 * GSTG)

template<int MODE, int SPLITK>
__global__ __launch_bounds__(256, 2) void bgemm(
    const __nv_bfloat16* __restrict__ A, const __nv_bfloat16* __restrict__ Bw,
    float* __restrict__ C, __nv_bfloat16* __restrict__ Cb,
    const float* __restrict__ bias,
    int M, int N, int K, int lda, int ldb, int ldc)
{
    constexpr int BK = 32;
    constexpr int MT = 2, NT = 8;

    extern __shared__ __nv_bfloat16 dsmem[];
    const uint32_t sbase = smem_u32(dsmem);

    if (SPLITK) {
        size_t ko = (size_t)blockIdx.z * K;
        A += ko; Bw += ko;
        C += (size_t)blockIdx.z * M * ldc;
    }

    const int tid = threadIdx.x, lane = tid & 31, warp = tid >> 5;
    const int m0 = blockIdx.y * 128, n0 = blockIdx.x * 128;
    const int wm = (warp >> 1) * 32, wn = (warp & 1) * 64;
    const int grp = lane >> 2, thr = lane & 3;

    const int a_row = wm + (lane & 15);
    const int a_col = (lane >> 4) * 8;
    const int b_row = wn + (lane & 7) + ((lane >> 4) << 3);
    const int b_col = ((lane >> 3) & 1) * 8;

    float acc[MT][NT][4];
#pragma unroll
    for (int i = 0; i < MT; i++)
#pragma unroll
        for (int j = 0; j < NT; j++)
#pragma unroll
            for (int q = 0; q < 4; q++) acc[i][j][q] = 0.0f;

    auto stage = [&](int kt, int s) {
        int k0 = kt << 5;
        uint32_t ab = sbase + s * GSTG;
        uint32_t bb = ab + GASZ;
#pragma unroll
        for (int i = 0; i < 2; i++) {
            int idx = tid + (i << 8);
            int r = idx >> 2, c = idx & 3;
            cp16(ab + (uint32_t)(r * (GLDS * 2) + c * 16),
                 A + (size_t)(m0 + r) * lda + k0 + c * 8);
        }
#pragma unroll
        for (int i = 0; i < 2; i++) {
            int idx = tid + (i << 8);
            int r = idx >> 2, c = idx & 3;
            int gr = n0 + r; if (gr >= N) gr = N - 1;
            cp16(bb + (uint32_t)(r * (GLDS * 2) + c * 16),
                 Bw + (size_t)gr * ldb + k0 + c * 8);
        }
        asm volatile("cp.async.commit_group;" ::: "memory");
    };

    auto comp = [&](int s) {
        uint32_t ab = sbase + s * GSTG;
        uint32_t bb = ab + GASZ;
#pragma unroll
        for (int kk = 0; kk < BK; kk += 16) {
            uint32_t af[MT][4], bf[NT][2];
#pragma unroll
            for (int mt = 0; mt < MT; mt++)
                ldsm4(ab + (uint32_t)(((a_row + mt * 16) * GLDS + kk + a_col) * 2),
                      af[mt][0], af[mt][1], af[mt][2], af[mt][3]);
#pragma unroll
            for (int np = 0; np < NT / 2; np++)
                ldsm4(bb + (uint32_t)(((b_row + np * 16) * GLDS + kk + b_col) * 2),
                      bf[2 * np][0], bf[2 * np][1], bf[2 * np + 1][0], bf[2 * np + 1][1]);
#pragma unroll
            for (int mt = 0; mt < MT; mt++)
#pragma unroll
                for (int nt = 0; nt < NT; nt++)
                    mma_bf16(acc[mt][nt], af[mt], bf[nt]);
        }
    };

    const int NC = K >> 5;
    stage(0, 0);
    stage(1, 1);
    for (int kt = 0; kt < NC; kt++) {
        if (kt + 1 < NC)
            asm volatile("cp.async.wait_group 1;" ::: "memory");
        else
            asm volatile("cp.async.wait_group 0;" ::: "memory");
        __syncthreads();
        comp(kt % 3);
        if (kt + 2 < NC) stage(kt + 2, (kt + 2) % 3);
    }

#pragma unroll
    for (int mt = 0; mt < MT; mt++) {
        int r0 = m0 + wm + mt * 16 + grp;
#pragma unroll
        for (int nt = 0; nt < NT; nt++) {
            int c0 = n0 + wn + nt * 8 + thr * 2;
            if (c0 < N) {
                float v0 = acc[mt][nt][0], v1 = acc[mt][nt][1];
                float v2 = acc[mt][nt][2], v3 = acc[mt][nt][3];
                if (MODE == 1) {
                    float b0 = bias[c0], b1 = bias[c0 + 1];
                    v0 = softp(v0 + b0); v1 = softp(v1 + b1);
                    v2 = softp(v2 + b0); v3 = softp(v3 + b1);
                }
                if (MODE == 3 || MODE == 1) {
                    __nv_bfloat162 h0, h1;
                    h0.x = __float2bfloat16(v0); h0.y = __float2bfloat16(v1);
                    h1.x = __float2bfloat16(v2); h1.y = __float2bfloat16(v3);
                    *(__nv_bfloat162*)&Cb[(size_t)r0 * ldc + c0]       = h0;
                    *(__nv_bfloat162*)&Cb[(size_t)(r0 + 8) * ldc + c0] = h1;
                } else {
                    *(float2*)&C[(size_t)r0 * ldc + c0]       = make_float2(v0, v1);
                    *(float2*)&C[(size_t)(r0 + 8) * ldc + c0] = make_float2(v2, v3);
                }
            }
        }
    }
}

// Deterministic fixed-order reduction of XPK split-K partials -> fp32 + bf16.
__global__ void xdbl_reduce(const float* __restrict__ part,
                            float* __restrict__ outf,
                            __nv_bfloat16* __restrict__ outb, int n)
{
    int i = blockIdx.x * blockDim.x + threadIdx.x;
    if (i >= n) return;
    float s = part[i];
#pragma unroll
    for (int z = 1; z < XPK; z++) s += part[(size_t)z * n + i];
    outf[i] = s;
    outb[i] = __float2bfloat16(s);
}

// ---------------------------------------------------------------------------
__global__ void f2bf_all(const float* __restrict__ s1, const float* __restrict__ s2,
                         const float* __restrict__ s3, const float* __restrict__ s4,
                         __nv_bfloat16* __restrict__ d1, __nv_bfloat16* __restrict__ d2,
                         __nv_bfloat16* __restrict__ d3, __nv_bfloat16* __restrict__ d4,
                         int n1, int n2, int n3, int n4)
{
    int i = blockIdx.x * blockDim.x + threadIdx.x;
    if (i < n1) { d1[i] = __float2bfloat16(s1[i]); return; }
    i -= n1;
    if (i < n2) { d2[i] = __float2bfloat16(s2[i]); return; }
    i -= n2;
    if (i < n3) { d3[i] = __float2bfloat16(s3[i]); return; }
    i -= n3;
    if (i < n4) d4[i] = __float2bfloat16(s4[i]);
}
__global__ void copy_kernel(const float* __restrict__ src, float* __restrict__ dst,
                            __nv_bfloat16* __restrict__ dstb, int n)
{
    int i = blockIdx.x * blockDim.x + threadIdx.x;
    if (i < n) { float v = src[i]; dst[i] = v; dstb[i] = __float2bfloat16(v); }
}

// Causal depthwise conv (width 4) + bias + SiLU; bf16 in/out, 2 channels/thread.
__global__ void conv_silu_kernel(const __nv_bfloat16* __restrict__ xz,
                                 const float* __restrict__ cw,
                                 const float* __restrict__ cb,
                                 __nv_bfloat16* __restrict__ xib)
{
    int idx = blockIdx.x * blockDim.x + threadIdx.x;   // over NTOK*DI/2
    if (idx >= NTOK * (DI / 2)) return;
    int d2 = idx % (DI / 2);
    int n  = idx / (DI / 2);
    int d  = d2 * 2;
    int t  = n % SEQ;

    float2 cbv = *(const float2*)(cb + d);
    float acc0 = cbv.x, acc1 = cbv.y;
    float4 w0 = *(const float4*)(cw + d * 4);
    float4 w1 = *(const float4*)(cw + d * 4 + 4);
    float wa0[4] = {w0.x, w0.y, w0.z, w0.w};
    float wa1[4] = {w1.x, w1.y, w1.z, w1.w};
#pragma unroll
    for (int k = 0; k < 4; k++) {
        int tt = t - 3 + k;
        if (tt >= 0) {
            __nv_bfloat162 v = *(const __nv_bfloat162*)&xz[(size_t)(n - 3 + k) * (2 * DI) + d];
            acc0 = fmaf(wa0[k], __bfloat162float(v.x), acc0);
            acc1 = fmaf(wa1[k], __bfloat162float(v.y), acc1);
        }
    }
    __nv_bfloat162 o;
    o.x = __float2bfloat16(siluf(acc0));
    o.y = __float2bfloat16(siluf(acc1));
    *(__nv_bfloat162*)&xib[(size_t)n * DI + d] = o;
}

// ---------------------------------------------------------------------------
// Chunked selective scan. delta is bf16 now.
// ---------------------------------------------------------------------------
__device__ __forceinline__ void scan_coeffs(
    const float* A_log, int d, int sub, float* Av, bool& trick)
{
#pragma unroll
    for (int i = 0; i < 4; i++)
        Av[i] = -__expf(A_log[d * DS + sub * 4 + i]);
    int e0 = sub * 4 + 1;
    trick = true;
#pragma unroll
    for (int i = 0; i < 4; i++)
        trick = trick && (fabsf(Av[i] + (float)(e0 + i)) < 3e-4f * (float)(e0 + i));
}
__device__ __forceinline__ void scan_dA(bool trick, const float* Av, int sub,
                                        float dlt, float* a)
{
    if (trick) {
        float r = fexp(-dlt);
        float r2 = r * r, r4 = r2 * r2;
        float p = r;
        if (sub & 1) p *= r4;
        if (sub & 2) p *= r4 * r4;
        a[0] = p; a[1] = p * r; a[2] = a[1] * r; a[3] = a[2] * r;
    } else {
        a[0] = fexp(dlt * Av[0]); a[1] = fexp(dlt * Av[1]);
        a[2] = fexp(dlt * Av[2]); a[3] = fexp(dlt * Av[3]);
    }
}

__global__ __launch_bounds__(128) void scanA(
    const float* __restrict__ xdbl, const __nv_bfloat16* __restrict__ delta,
    const __nv_bfloat16* __restrict__ xi, const float* __restrict__ A_log,
    const float* __restrict__ Dv,
    __nv_bfloat16* __restrict__ ypart, float* __restrict__ apv,
    float* __restrict__ hev)
{
    int gt  = blockIdx.x * 128 + threadIdx.x;
    int sub = gt & 3;
    int ch  = gt >> 2;                 // (b*DI+d)*NCH + c
    if (ch >= NB * DI * NCH) return;
    int c  = ch % NCH;
    int bd = ch / NCH;
    int d  = bd % DI, b = bd / DI;

    float Av[4]; bool trick;
    scan_coeffs(A_log, d, sub, Av, trick);
    float Dd = Dv[d];

    float h[4] = {0.f, 0.f, 0.f, 0.f};
    float ap[4] = {1.f, 1.f, 1.f, 1.f};
    const int base = b * SEQ + c * CL;

    for (int t = 0; t < CL; t++) {
        int n = base + t;
        float dlt = __bfloat162float(__ldg(&delta[(size_t)n * DI + d]));
        float u   = __bfloat162float(__ldg(&xi[(size_t)n * DI + d]));
        float4 Bv = __ldg((const float4*)(xdbl + (size_t)n * 96 + 64 + sub * 4));
        float4 Cv = __ldg((const float4*)(xdbl + (size_t)n * 96 + 80 + sub * 4));
        float a[4];
        scan_dA(trick, Av, sub, dlt, a);
        float du = dlt * u;
#pragma unroll
        for (int i = 0; i < 4; i++) ap[i] *= a[i];
        h[0] = fmaf(a[0], h[0], Bv.x * du);
        h[1] = fmaf(a[1], h[1], Bv.y * du);
        h[2] = fmaf(a[2], h[2], Bv.z * du);
        h[3] = fmaf(a[3], h[3], Bv.w * du);
        float yp = h[0] * Cv.x;
        yp = fmaf(h[1], Cv.y, yp);
        yp = fmaf(h[2], Cv.z, yp);
        yp = fmaf(h[3], Cv.w, yp);
        yp += __shfl_xor_sync(0xffffffffu, yp, 1);
        yp += __shfl_xor_sync(0xffffffffu, yp, 2);
        if (sub == 0)
            ypart[(size_t)n * DI + d] = __float2bfloat16(yp + u * Dd);
    }
#pragma unroll
    for (int i = 0; i < 4; i++) {
        apv[ch * 16 + sub * 4 + i] = ap[i];
        hev[ch * 16 + sub * 4 + i] = h[i];
    }
}

__global__ void scanB(const float* __restrict__ apv, const float* __restrict__ hev,
                      float* __restrict__ h0v)
{
    int i = blockIdx.x * 256 + threadIdx.x;   // over NB*DI*DS
    if (i >= NB * DI * DS) return;
    int s  = i & 15;
    int bd = i >> 4;
    float h = 0.0f;
#pragma unroll
    for (int c = 0; c < NCH; c++) {
        int idx = (bd * NCH + c) * 16 + s;
        h0v[idx] = h;
        h = fmaf(apv[idx], h, hev[idx]);
    }
}

__global__ __launch_bounds__(128) void scanC(
    const float* __restrict__ xdbl, const __nv_bfloat16* __restrict__ delta,
    const __nv_bfloat16* __restrict__ xz, const float* __restrict__ A_log,
    const __nv_bfloat16* __restrict__ ypart, const float* __restrict__ h0v,
    __nv_bfloat16* __restrict__ ybf)
{
    int gt  = blockIdx.x * 128 + threadIdx.x;
    int sub = gt & 3;
    int ch  = gt >> 2;
    if (ch >= NB * DI * NCH) return;
    int c  = ch % NCH;
    int bd = ch / NCH;
    int d  = bd % DI, b = bd / DI;

    float Av[4]; bool trick;
    scan_coeffs(A_log, d, sub, Av, trick);

    float h0[4], P[4] = {1.f, 1.f, 1.f, 1.f};
#pragma unroll
    for (int i = 0; i < 4; i++) h0[i] = h0v[ch * 16 + sub * 4 + i];

    const int base = b * SEQ + c * CL;
    for (int t = 0; t < CL; t++) {
        int n = base + t;
        float dlt = __bfloat162float(__ldg(&delta[(size_t)n * DI + d]));
        float4 Cv = __ldg((const float4*)(xdbl + (size_t)n * 96 + 80 + sub * 4));
        float a[4];
        scan_dA(trick, Av, sub, dlt, a);
#pragma unroll
        for (int i = 0; i < 4; i++) P[i] *= a[i];
        float corr = (P[0] * h0[0]) * Cv.x;
        corr = fmaf(P[1] * h0[1], Cv.y, corr);
        corr = fmaf(P[2] * h0[2], Cv.z, corr);
        corr = fmaf(P[3] * h0[3], Cv.w, corr);
        corr += __shfl_xor_sync(0xffffffffu, corr, 1);
        corr += __shfl_xor_sync(0xffffffffu, corr, 2);
        if (sub == 0) {
            float y = __bfloat162float(ypart[(size_t)n * DI + d]) + corr;
            float zv = __bfloat162float(__ldg(&xz[(size_t)n * (2 * DI) + DI + d]));
            ybf[(size_t)n * DI + d] = __float2bfloat16(y * siluf(zv));
        }
    }
}

// LayerNorm with fused residual: x = LN(tmp + x)*w + b; fp32 + bf16 outputs.
__global__ __launch_bounds__(256) void ln_kernel(
    const float* __restrict__ tmp, float* __restrict__ x,
    __nv_bfloat16* __restrict__ xb,
    const float* __restrict__ w, const float* __restrict__ bb)
{
    int n = blockIdx.x;
    int tid = threadIdx.x;
    __shared__ float sred[40];

    float v[4];
    float s = 0.0f;
#pragma unroll
    for (int i = 0; i < 4; i++) {
        int c = tid + 256 * i;
        v[i] = tmp[(size_t)n * DM + c] + x[(size_t)n * DM + c];
        s += v[i];
    }
    for (int o = 16; o; o >>= 1) s += __shfl_xor_sync(0xffffffffu, s, o);
    if ((tid & 31) == 0) sred[tid >> 5] = s;
    __syncthreads();
    if (tid < 8) {
        s = sred[tid];
        for (int o = 4; o; o >>= 1) s += __shfl_xor_sync(0xffu, s, o);
        if (tid == 0) sred[32] = s;
    }
    __syncthreads();
    float mu = sred[32] * (1.0f / DM);

    float s2 = 0.0f;
#pragma unroll
    for (int i = 0; i < 4; i++) {
        float dv = v[i] - mu;
        s2 += dv * dv;
    }
    for (int o = 16; o; o >>= 1) s2 += __shfl_xor_sync(0xffffffffu, s2, o);
    if ((tid & 31) == 0) sred[tid >> 5] = s2;
    __syncthreads();
    if (tid < 8) {
        s2 = sred[tid];
        for (int o = 4; o; o >>= 1) s2 += __shfl_xor_sync(0xffu, s2, o);
        if (tid == 0) sred[33] = s2;
    }
    __syncthreads();
    float inv = rsqrtf(sred[33] * (1.0f / DM) + 1e-5f);

#pragma unroll
    for (int i = 0; i < 4; i++) {
        int c = tid + 256 * i;
        float o = (v[i] - mu) * inv * w[c] + bb[c];
        x[(size_t)n * DM + c] = o;
        xb[(size_t)n * DM + c] = __float2bfloat16(o);
    }
}

// Layer-6 shortcut: out_proj restricted to last token of each batch.
__global__ __launch_bounds__(256) void final_out_kernel(
    const __nv_bfloat16* __restrict__ y, const __nv_bfloat16* __restrict__ outw,
    float* __restrict__ tmp4)
{
    int b = blockIdx.x, col = blockIdx.y * 256 + threadIdx.x;
    const __nv_bfloat16* yr = y + (size_t)(b * SEQ + SEQ - 1) * DI;
    const __nv_bfloat16* wr = outw + (size_t)col * DI;
    __shared__ __nv_bfloat16 ys[DI];
    for (int i = threadIdx.x; i < DI; i += 256) ys[i] = yr[i];
    __syncthreads();
    float s = 0.0f;
#pragma unroll 4
    for (int k = 0; k < DI; k += 8) {
        uint4 wv = *(const uint4*)(wr + k);
        const __nv_bfloat162* w2 = (const __nv_bfloat162*)&wv;
        const __nv_bfloat162* y2 = (const __nv_bfloat162*)&ys[k];
#pragma unroll
        for (int j = 0; j < 4; j++) {
            s = fmaf(__bfloat162float(y2[j].x), __bfloat162float(w2[j].x), s);
            s = fmaf(__bfloat162float(y2[j].y), __bfloat162float(w2[j].y), s);
        }
    }
    tmp4[b * DM + col] = s;
}

// Layer-6 LN + prediction fused, last tokens only.
__global__ __launch_bounds__(256) void final_ln_pred(
    const float* __restrict__ tmp4, const float* __restrict__ x,
    const float* __restrict__ w, const float* __restrict__ bb,
    const float* __restrict__ pw, const float* __restrict__ pb,
    float* __restrict__ out)
{
    int b = blockIdx.x;
    int tid = threadIdx.x;
    __shared__ float sred[40];
    const float* row = x + (size_t)(b * SEQ + SEQ - 1) * DM;

    float v[4];
    float s = 0.0f;
#pragma unroll
    for (int i = 0; i < 4; i++) {
        int c = tid + 256 * i;
        v[i] = tmp4[b * DM + c] + row[c];
        s += v[i];
    }
    for (int o = 16; o; o >>= 1) s += __shfl_xor_sync(0xffffffffu, s, o);
    if ((tid & 31) == 0) sred[tid >> 5] = s;
    __syncthreads();
    if (tid < 8) {
        s = sred[tid];
        for (int o = 4; o; o >>= 1) s += __shfl_xor_sync(0xffu, s, o);
        if (tid == 0) sred[32] = s;
    }
    __syncthreads();
    float mu = sred[32] * (1.0f / DM);

    float s2 = 0.0f;
#pragma unroll
    for (int i = 0; i < 4; i++) { float dv = v[i] - mu; s2 += dv * dv; }
    for (int o = 16; o; o >>= 1) s2 += __shfl_xor_sync(0xffffffffu, s2, o);
    if ((tid & 31) == 0) sred[tid >> 5] = s2;
    __syncthreads();
    if (tid < 8) {
        s2 = sred[tid];
        for (int o = 4; o; o >>= 1) s2 += __shfl_xor_sync(0xffu, s2, o);
        if (tid == 0) sred[33] = s2;
    }
    __syncthreads();
    float inv = rsqrtf(sred[33] * (1.0f / DM) + 1e-5f);

    float s3 = 0.0f;
#pragma unroll
    for (int i = 0; i < 4; i++) {
        int c = tid + 256 * i;
        float o = (v[i] - mu) * inv * w[c] + bb[c];
        s3 = fmaf(o, pw[c], s3);
    }
    for (int o = 16; o; o >>= 1) s3 += __shfl_xor_sync(0xffffffffu, s3, o);
    if ((tid & 31) == 0) sred[tid >> 5] = s3;
    __syncthreads();
    if (tid < 8) {
        s3 = sred[tid];
        for (int o = 4; o; o >>= 1) s3 += __shfl_xor_sync(0xffu, s3, o);
        if (tid == 0) out[b] = s3 + pb[0];
    }
}

// ---------------------------------------------------------------------------
extern "C" void kernel_launch(void* const* d_in, const int* in_sizes, int n_in,
                              void* d_out, int out_size)
{
    const float* x_in  = (const float*)d_in[0];
    const float* inw   = (const float*)d_in[1];
    const float* convw = (const float*)d_in[2];
    const float* convb = (const float*)d_in[3];
    const float* xpw   = (const float*)d_in[4];
    const float* dtw   = (const float*)d_in[5];
    const float* dtb   = (const float*)d_in[6];
    const float* Alog  = (const float*)d_in[7];
    const float* Dv    = (const float*)d_in[8];
    const float* outw  = (const float*)d_in[9];
    const float* lnw   = (const float*)d_in[10];
    const float* lnb   = (const float*)d_in[11];
    const float* predw = (const float*)d_in[12];
    const float* predb = (const float*)d_in[13];
    float* out = (float*)d_out;

    float *p_x, *p_xdbl, *p_xdp, *p_tmp, *p_tmp4;
    float *p_ap, *p_he, *p_h0;
    __nv_bfloat16 *p_dltbf, *p_xzbf, *p_ypbf, *p_xbf, *p_xibf, *p_ybf, *p_xdblbf;
    __nv_bfloat16 *p_inwb, *p_xpwb, *p_dtwb, *p_outwb;
    cudaGetSymbolAddress((void**)&p_x, g_x);
    cudaGetSymbolAddress((void**)&p_xdbl, g_xdbl);
    cudaGetSymbolAddress((void**)&p_xdp, g_xdp);
    cudaGetSymbolAddress((void**)&p_tmp, g_tmp);
    cudaGetSymbolAddress((void**)&p_tmp4, g_tmp4);
    cudaGetSymbolAddress((void**)&p_ap, g_ap);
    cudaGetSymbolAddress((void**)&p_he, g_he);
    cudaGetSymbolAddress((void**)&p_h0, g_h0);
    cudaGetSymbolAddress((void**)&p_dltbf, g_deltabf);
    cudaGetSymbolAddress((void**)&p_xzbf, g_xzbf);
    cudaGetSymbolAddress((void**)&p_ypbf, g_ypbf);
    cudaGetSymbolAddress((void**)&p_xbf, g_xbf);
    cudaGetSymbolAddress((void**)&p_xibf, g_xibf);
    cudaGetSymbolAddress((void**)&p_ybf, g_ybf);
    cudaGetSymbolAddress((void**)&p_xdblbf, g_xdblbf);
    cudaGetSymbolAddress((void**)&p_inwb, g_inw_bf);
    cudaGetSymbolAddress((void**)&p_xpwb, g_xpw_bf);
    cudaGetSymbolAddress((void**)&p_dtwb, g_dtw_bf);
    cudaGetSymbolAddress((void**)&p_outwb, g_outw_bf);

    cudaFuncSetAttribute(bgemm<0,0>, cudaFuncAttributeMaxDynamicSharedMemorySize, GSMEM);
    cudaFuncSetAttribute(bgemm<1,0>, cudaFuncAttributeMaxDynamicSharedMemorySize, GSMEM);
    cudaFuncSetAttribute(bgemm<3,0>, cudaFuncAttributeMaxDynamicSharedMemorySize, GSMEM);
    cudaFuncSetAttribute(bgemm<0,1>, cudaFuncAttributeMaxDynamicSharedMemorySize, GSMEM);

    // One launch for all weight conversions
    {
        int n1 = NL * 2 * DI * DM, n2 = NL * 96 * DI, n3 = NL * DI * DR, n4 = NL * DM * DI;
        int nt = n1 + n2 + n3 + n4;
        f2bf_all<<<(nt + 255) / 256, 256>>>(inw, xpw, dtw, outw,
                                            p_inwb, p_xpwb, p_dtwb, p_outwb,
                                            n1, n2, n3, n4);
    }
    copy_kernel<<<(NTOK * DM + 255) / 256, 256>>>(x_in, p_x, p_xbf, NTOK * DM);

    for (int l = 0; l < NL; l++) {
        // 1) xz = x @ in_proj_w^T  (bf16-only output)
        bgemm<3,0><<<dim3((2 * DI) / 128, NTOK / 128), 256, GSMEM>>>(
            p_xbf, p_inwb + (size_t)l * 2 * DI * DM, nullptr, p_xzbf, nullptr,
            NTOK, 2 * DI, DM, DM, DM, 2 * DI);

        // 2) xi = silu(causal_conv(xz[:, :DI]))  (bf16, 2 ch/thread)
        conv_silu_kernel<<<(NTOK * (DI / 2) + 255) / 256, 256>>>(
            p_xzbf, convw + (size_t)l * DI * 4, convb + (size_t)l * DI, p_xibf);

        // 3) x_dbl = xi @ x_proj_w^T  — split-K x4 + deterministic reduce
        bgemm<0,1><<<dim3(1, NTOK / 128, XPK), 256, GSMEM>>>(
            p_xibf, p_xpwb + (size_t)l * 96 * DI, p_xdp, nullptr, nullptr,
            NTOK, 96, DI / XPK, DI, DI, 96);
        xdbl_reduce<<<(NTOK * 96 + 255) / 256, 256>>>(
            p_xdp, p_xdbl, p_xdblbf, NTOK * 96);

        // 4) delta = softplus(x_dbl[:, :64] @ dt_w^T + dt_b)  -> bf16
        bgemm<1,0><<<dim3(DI / 128, NTOK / 128), 256, GSMEM>>>(
            p_xdblbf, p_dtwb + (size_t)l * DI * DR, nullptr, p_dltbf,
            dtb + (size_t)l * DI,
            NTOK, DI, DR, 96, DR, DI);

        // 5) chunked selective scan
        scanA<<<(NB * DI * NCH * 4) / 128, 128>>>(
            p_xdbl, p_dltbf, p_xibf, Alog + (size_t)l * DI * DS,
            Dv + (size_t)l * DI, p_ypbf, p_ap, p_he);
        scanB<<<(NB * DI * DS + 255) / 256, 256>>>(p_ap, p_he, p_h0);
        scanC<<<(NB * DI * NCH * 4) / 128, 128>>>(
            p_xdbl, p_dltbf, p_xzbf, Alog + (size_t)l * DI * DS,
            p_ypbf, p_h0, p_ybf);

        if (l < NL - 1) {
            // 6) tmp = y @ out_proj_w^T  (fp32 for LN residual)
            bgemm<0,0><<<dim3(DM / 128, NTOK / 128), 256, GSMEM>>>(
                p_ybf, p_outwb + (size_t)l * DM * DI, p_tmp, nullptr, nullptr,
                NTOK, DM, DI, DI, DI, DM);

            // 7) x = LN(tmp + x)
            ln_kernel<<<NTOK, 256>>>(p_tmp, p_x, p_xbf,
                                     lnw + (size_t)l * DM, lnb + (size_t)l * DM);
        } else {
            final_out_kernel<<<dim3(NB, DM / 256), 256>>>(
                p_ybf, p_outwb + (size_t)l * DM * DI, p_tmp4);
            final_ln_pred<<<NB, 256>>>(
                p_tmp4, p_x, lnw + (size_t)l * DM, lnb + (size_t)l * DM,
                predw, predb, out);
        }
    }
}